// round 12
// baseline (speedup 1.0000x reference)
#include <cuda_runtime.h>
#include <math.h>
#include <stdint.h>

#define NB 65536
#define ND 768
#define NS 64
#define NT 17
#define T_MAX 2.0f
#define DT (T_MAX / (float)NT)
#define EPSV 1e-8f
#define NCH 24                 // k chunks of 32
#define NKK (ND / 8)           // 96
#define ECF_BLOCKS (16 * NS)   // 1024

typedef unsigned long long ull;

// ---------------- device scratch ----------------
__device__ float  g_projT[NS * NB];
__device__ float4 g_dirsFrag[NKK * 4 * 32];   // 196KB, frag-ready tf32
__device__ float  g_colsum[ND];
__device__ float  g_colsq[ND];
__device__ float  g_psum[NS];
__device__ float  g_psq[NS];
__device__ float  g_ecfr[NT * NS];
__device__ float  g_ecfi[NT * NS];
__device__ unsigned int g_done;

// ---------------- ptx helpers ----------------
__device__ __forceinline__ uint32_t f2tf(float f) {
    uint32_t r; asm("cvt.rna.tf32.f32 %0, %1;" : "=r"(r) : "f"(f)); return r;
}
__device__ __forceinline__ void mma8(float* c, const uint32_t* a,
                                     uint32_t b0, uint32_t b1) {
    asm volatile(
        "mma.sync.aligned.m16n8k8.row.col.f32.tf32.tf32.f32 "
        "{%0,%1,%2,%3},{%4,%5,%6,%7},{%8,%9},{%0,%1,%2,%3};"
        : "+f"(c[0]), "+f"(c[1]), "+f"(c[2]), "+f"(c[3])
        : "r"(a[0]), "r"(a[1]), "r"(a[2]), "r"(a[3]), "r"(b0), "r"(b1));
}
__device__ __forceinline__ uint32_t smem_u32(const void* p) {
    uint32_t a;
    asm("{ .reg .u64 t; cvta.to.shared.u64 t, %1; cvt.u32.u64 %0, t; }" : "=r"(a) : "l"(p));
    return a;
}
__device__ __forceinline__ void cp16(uint32_t s, const void* g) {
    asm volatile("cp.async.cg.shared.global [%0], [%1], 16;" :: "r"(s), "l"(g));
}
#define CP_COMMIT() asm volatile("cp.async.commit_group;" ::: "memory")
#define CP_WAIT2()  asm volatile("cp.async.wait_group 2;" ::: "memory")
#define CP_WAIT0()  asm volatile("cp.async.wait_group 0;" ::: "memory")
__device__ __forceinline__ float lds32(uint32_t a) {
    float v; asm volatile("ld.shared.f32 %0, [%1];" : "=f"(v) : "r"(a)); return v;
}
__device__ __forceinline__ float4 lds128(uint32_t a) {
    float4 v;
    asm volatile("ld.shared.v4.f32 {%0,%1,%2,%3}, [%4];"
                 : "=f"(v.x), "=f"(v.y), "=f"(v.z), "=f"(v.w) : "r"(a));
    return v;
}

// packed f32x2 helpers
__device__ __forceinline__ ull pack2(float lo, float hi) {
    ull r; asm("mov.b64 %0, {%1, %2};" : "=l"(r) : "f"(lo), "f"(hi)); return r;
}
__device__ __forceinline__ void fma2(ull& d, ull a, ull b) {
    asm("fma.rn.f32x2 %0, %1, %2, %0;" : "+l"(d) : "l"(a), "l"(b));
}
__device__ __forceinline__ ull add2(ull a, ull b) {
    ull r; asm("add.rn.f32x2 %0, %1, %2;" : "=l"(r) : "l"(a), "l"(b)); return r;
}
__device__ __forceinline__ ull neg2(ull a) {
    return a ^ 0x8000000080000000ull;
}
__device__ __forceinline__ float2 unpk(ull v) {
    float2 f; asm("mov.b64 {%0, %1}, %2;" : "=f"(f.x), "=f"(f.y) : "l"(v)); return f;
}

// ---------------- kernel 1: fused init + dirnorm + frag build --------------
// 48 blocks x 256 threads. Each block: zero its slice of global accumulators,
// compute all 64 column norms from dirs (L2-hit after block 0), write 256 frags.
__global__ __launch_bounds__(256) void k_prep(const float* __restrict__ dirs) {
    __shared__ float red[4][64];
    __shared__ float sn[64];
    const int tid = threadIdx.x;
    const int gidx = blockIdx.x * 256 + tid;     // 0..12287

    // zero accumulators (graph is replayed)
    if (gidx < ND)      { g_colsum[gidx] = 0.f; g_colsq[gidx] = 0.f; }
    if (gidx < NS)      { g_psum[gidx]   = 0.f; g_psq[gidx]   = 0.f; }
    if (gidx < NT * NS) { g_ecfr[gidx]   = 0.f; g_ecfi[gidx]  = 0.f; }
    if (gidx == 0)      g_done = 0;

    // column norms: s = tid&63, quarter q = tid>>6 covers d = q,q+4,...
    const int s = tid & 63, q = tid >> 6;
    float acc = 0.f;
    #pragma unroll 8
    for (int d = q; d < ND; d += 4) {
        float v = dirs[(size_t)d * NS + s];
        acc += v * v;
    }
    red[q][s] = acc;
    __syncthreads();
    if (tid < 64)
        sn[tid] = 1.0f / sqrtf(red[0][tid] + red[1][tid] + red[2][tid] + red[3][tid]);
    __syncthreads();

    // frag build (same mapping as before)
    {
        int kk = gidx >> 7, rem = gidx & 127;
        int mt = rem >> 5, lane = rem & 31;
        int g = lane >> 2, t = lane & 3;
        int s0 = mt * 16 + g;
        int k0 = kk * 8 + t;
        float i0 = sn[s0], i1 = sn[s0 + 8];
        float4 v;
        v.x = __uint_as_float(f2tf(dirs[(size_t)k0 * NS + s0]       * i0));
        v.y = __uint_as_float(f2tf(dirs[(size_t)k0 * NS + s0 + 8]   * i1));
        v.z = __uint_as_float(f2tf(dirs[(size_t)(k0 + 4) * NS + s0]     * i0));
        v.w = __uint_as_float(f2tf(dirs[(size_t)(k0 + 4) * NS + s0 + 8] * i1));
        g_dirsFrag[gidx] = v;
    }
}

// ---------------- kernel 2: staged HMMA tf32 GEMM + colstats + psums -------
// (unchanged from the 90.2us/51.6us R11 version)
#define ZRING (8 * 2 * 4096)          // 64 KB
#define FROFF ZRING
#define SMTOT (ZRING + 3 * 8192)      // 88 KB dynamic

__global__ __launch_bounds__(256, 2) void k_gemm(const float* __restrict__ z) {
    extern __shared__ __align__(128) char smem[];
    __shared__ float scol_s[ND], scol_q[ND];
    __shared__ float ssum[64], ssq[64];

    const uint32_t sb = smem_u32(smem);
    const uint32_t fb = sb + FROFF;
    const int tid = threadIdx.x;
    const int wid = tid >> 5, lane = tid & 31;
    const int g = lane >> 2, t = lane & 3;
    const int nwarp = blockIdx.x * 256 + wid * 32;

    for (int i = tid; i < ND; i += 256) { scol_s[i] = 0.f; scol_q[i] = 0.f; }
    if (tid < 64) { ssum[tid] = 0.f; ssq[tid] = 0.f; }
    __syncthreads();

    const uint32_t wstage = sb + wid * 8192;
    const int fr = lane >> 3, fu = lane & 7;
    const float* zsrc = z + (size_t)nwarp * ND;

    #define FILL_Z(ch) do { \
        uint32_t dst = wstage + ((ch) & 1) * 4096; \
        const float* srcb = zsrc + (ch) * 32; \
        _Pragma("unroll") \
        for (int i = 0; i < 8; i++) { \
            int r = i * 4 + fr; \
            cp16(dst + r * 128 + ((fu ^ (r & 7)) << 4), \
                 srcb + (size_t)r * ND + fu * 4); \
        } \
        CP_COMMIT(); \
    } while (0)

    #define FILL_F(ch) do { \
        uint32_t dst = fb + ((ch) % 3) * 8192 + tid * 32; \
        const float4* srcb = g_dirsFrag + (ch) * 512 + tid * 2; \
        cp16(dst,      srcb); \
        cp16(dst + 16, srcb + 1); \
        CP_COMMIT(); \
    } while (0)

    FILL_F(0); FILL_Z(0); FILL_F(1); FILL_Z(1);

    float c[4][4][4];
    #pragma unroll
    for (int mt = 0; mt < 4; mt++)
        #pragma unroll
        for (int nt = 0; nt < 4; nt++)
            #pragma unroll
            for (int r = 0; r < 4; r++) c[mt][nt][r] = 0.f;

    for (int ch = 0; ch < NCH; ch++) {
        if (ch < NCH - 1) { CP_WAIT2(); } else { CP_WAIT0(); }
        __syncthreads();

        if (ch + 2 < NCH) FILL_F(ch + 2);

        const uint32_t zstage = wstage + (ch & 1) * 4096;
        const uint32_t fstage = fb + (ch % 3) * 8192;

        #pragma unroll
        for (int kk = 0; kk < 4; kk++) {
            uint32_t a[4][4];
            #pragma unroll
            for (int mt = 0; mt < 4; mt++) {
                float4 v = lds128(fstage + ((kk * 128 + mt * 32 + lane) << 4));
                a[mt][0] = __float_as_uint(v.x);
                a[mt][1] = __float_as_uint(v.y);
                a[mt][2] = __float_as_uint(v.z);
                a[mt][3] = __float_as_uint(v.w);
            }
            uint32_t b0[4], b1[4];
            #pragma unroll
            for (int nt = 0; nt < 4; nt++) {
                int row = nt * 8 + g;
                uint32_t base = zstage + row * 128 + t * 4;
                b0[nt] = __float_as_uint(lds32(base + (((2 * kk)     ^ g) << 4)));
                b1[nt] = __float_as_uint(lds32(base + (((2 * kk + 1) ^ g) << 4)));
            }
            #pragma unroll
            for (int mt = 0; mt < 4; mt++)
                #pragma unroll
                for (int nt = 0; nt < 4; nt++)
                    mma8(c[mt][nt], a[mt], b0[nt], b1[nt]);
        }

        {
            const int cu = lane >> 2, co = (lane & 3) * 4;
            float cs = 0.f, cq = 0.f;
            #pragma unroll
            for (int r = 0; r < 32; r++) {
                float v = lds32(zstage + r * 128 + ((cu ^ (r & 7)) << 4) + co);
                cs += v; cq += v * v;
            }
            atomicAdd(&scol_s[ch * 32 + lane], cs);
            atomicAdd(&scol_q[ch * 32 + lane], cq);
        }

        if (ch + 2 < NCH) FILL_Z(ch + 2);
    }

    #pragma unroll
    for (int mt = 0; mt < 4; mt++) {
        float su0 = 0.f, su1 = 0.f, sq0 = 0.f, sq1 = 0.f;
        int s0 = mt * 16 + g;
        #pragma unroll
        for (int nt = 0; nt < 4; nt++) {
            float d0 = c[mt][nt][0], d1 = c[mt][nt][1];
            float d2 = c[mt][nt][2], d3 = c[mt][nt][3];
            int n = nwarp + nt * 8 + t * 2;
            *(float2*)(g_projT + (size_t)s0 * NB + n)       = make_float2(d0, d1);
            *(float2*)(g_projT + (size_t)(s0 + 8) * NB + n) = make_float2(d2, d3);
            su0 += d0 + d1; sq0 += d0 * d0 + d1 * d1;
            su1 += d2 + d3; sq1 += d2 * d2 + d3 * d3;
        }
        #pragma unroll
        for (int off = 1; off < 4; off <<= 1) {
            su0 += __shfl_xor_sync(0xffffffffu, su0, off);
            sq0 += __shfl_xor_sync(0xffffffffu, sq0, off);
            su1 += __shfl_xor_sync(0xffffffffu, su1, off);
            sq1 += __shfl_xor_sync(0xffffffffu, sq1, off);
        }
        if (t == 0) {
            atomicAdd(&ssum[s0], su0);     atomicAdd(&ssq[s0], sq0);
            atomicAdd(&ssum[s0 + 8], su1); atomicAdd(&ssq[s0 + 8], sq1);
        }
    }
    __syncthreads();
    if (tid < 64) {
        atomicAdd(&g_psum[tid], ssum[tid]);
        atomicAdd(&g_psq[tid],  ssq[tid]);
    }
    #pragma unroll
    for (int rep = 0; rep < 3; rep++) {
        int col = rep * 256 + tid;
        atomicAdd(&g_colsum[col], scol_s[col]);
        atomicAdd(&g_colsq[col],  scol_q[col]);
    }
}

// ---------------- kernel 3: ECF (Chebyshev f32x2) + fused final loss -------
__global__ __launch_bounds__(256) void k_ecf(float* __restrict__ out) {
    __shared__ float red[256];
    __shared__ int slast;
    int s = blockIdx.y;
    float pmean = g_psum[s] / (float)NB;
    float pvar = (g_psq[s] - (float)NB * pmean * pmean) / (float)(NB - 1);
    float invstd = 1.0f / (sqrtf(fmaxf(pvar, 0.f)) + EPSV);

    size_t basep = (size_t)s * NB + blockIdx.x * 4096;
    const float2* src = (const float2*)(g_projT + basep);

    ull CR[NT], CI[NT];
    #pragma unroll
    for (int j = 0; j < NT; j++) { CR[j] = 0ull; CI[j] = 0ull; }

    #pragma unroll 2
    for (int i = 0; i < 8; i++) {
        float2 pv = src[threadIdx.x + i * 256];
        float p0 = (pv.x - pmean) * invstd;
        float p1 = (pv.y - pmean) * invstd;
        float c0, s0, c1v, s1v;
        __sincosf(DT * p0, &s0, &c0);
        __sincosf(DT * p1, &s1v, &c1v);
        ull cc = pack2(c0, c1v);
        ull ss = pack2(s0, s1v);
        ull twoc = add2(cc, cc);
        ull ncp = pack2(-1.f, -1.f);
        ull nsp = 0ull;
        #pragma unroll
        for (int j = 0; j < NT; j++) {
            CR[j] = add2(CR[j], cc);
            CI[j] = add2(CI[j], ss);
            ull cn = ncp; fma2(cn, twoc, cc);
            ull sn = nsp; fma2(sn, twoc, ss);
            ncp = neg2(cc); nsp = neg2(ss);
            cc = cn; ss = sn;
        }
    }

    unsigned msk = 0xffffffffu;
    #pragma unroll
    for (int j = 0; j < NT; j++) {
        float2 r2 = unpk(CR[j]);
        float2 i2 = unpk(CI[j]);
        float r = r2.x + r2.y, im = i2.x + i2.y;
        #pragma unroll
        for (int off = 16; off; off >>= 1) {
            r  += __shfl_down_sync(msk, r,  off);
            im += __shfl_down_sync(msk, im, off);
        }
        if ((threadIdx.x & 31) == 0) {
            atomicAdd(&g_ecfr[j * NS + s], r);
            atomicAdd(&g_ecfi[j * NS + s], im);
        }
    }

    // completion: each atomic-issuing thread fences its own writes
    if ((threadIdx.x & 31) == 0) __threadfence();
    __syncthreads();
    if (threadIdx.x == 0) {
        unsigned r = atomicAdd(&g_done, 1u);
        slast = (r == ECF_BLOCKS - 1);
    }
    __syncthreads();
    if (!slast) return;
    __threadfence();   // acquire: all other blocks' fenced writes now visible

    // ---- final scalar loss (last block, 256 threads) ----
    int t = threadIdx.x;
    float acc = 0.f;
    for (int d = t; d < ND; d += 256) {
        float mean = g_colsum[d] / (float)NB;
        float var = (g_colsq[d] - (float)NB * mean * mean) / (float)(NB - 1);
        float stdv = sqrtf(fmaxf(var, 0.f));
        acc += fmaxf(1.0f - stdv, 0.f) * (1.0f / (float)ND);
    }
    for (int idx = t; idx < NT * NS; idx += 256) {
        int j = idx / NS;
        float tj = DT * (float)(j + 1);
        float er = g_ecfr[idx] / (float)NB;
        float ei = g_ecfi[idx] / (float)NB;
        float tcf = expf(-0.5f * tj * tj);
        float term = er * er + ei * ei - 2.0f * er * tcf + tcf * tcf;
        float w = DT * ((j == 0 || j == NT - 1) ? 0.5f : 1.0f);
        acc += w * term * (1.0f / (float)NS);
    }
    red[t] = acc;
    __syncthreads();
    for (int off = 128; off; off >>= 1) {
        if (t < off) red[t] += red[t + off];
        __syncthreads();
    }
    if (t == 0) out[0] = red[0];
}

// ---------------- launch -----------------------------------------------------
extern "C" void kernel_launch(void* const* d_in, const int* in_sizes, int n_in,
                              void* d_out, int out_size) {
    const float* z    = (const float*)d_in[0];   // [65536, 768]
    const float* dirs = (const float*)d_in[1];   // [768, 64]
    float* out = (float*)d_out;

    cudaFuncSetAttribute(k_gemm, cudaFuncAttributeMaxDynamicSharedMemorySize, SMTOT);

    k_prep<<<48, 256>>>(dirs);
    k_gemm<<<NB / 256, 256, SMTOT>>>(z);
    k_ecf<<<dim3(16, NS), 256>>>(out);
}

// round 13
// speedup vs baseline: 1.1048x; 1.1048x over previous
#include <cuda_runtime.h>
#include <math.h>
#include <stdint.h>

#define NB 65536
#define ND 768
#define NS 64
#define NT 17
#define T_MAX 2.0f
#define DT (T_MAX / (float)NT)
#define EPSV 1e-8f
#define NCH 24                 // k chunks of 32
#define NKK (ND / 8)           // 96
#define ECF_BLOCKS (16 * NS)   // 1024

typedef unsigned long long ull;

// ---------------- device scratch ----------------
__device__ float  g_projT[NS * NB];
__device__ float4 g_dirsFrag[NKK * 4 * 32];   // frag-ready tf32
__device__ float  g_norm2[NS];
__device__ float  g_colsum[ND];
__device__ float  g_colsq[ND];
__device__ float  g_psum[NS];
__device__ float  g_psq[NS];
__device__ float  g_ecfr[NT * NS];
__device__ float  g_ecfi[NT * NS];
__device__ unsigned int g_done;

// ---------------- ptx helpers ----------------
__device__ __forceinline__ uint32_t f2tf(float f) {
    uint32_t r; asm("cvt.rna.tf32.f32 %0, %1;" : "=r"(r) : "f"(f)); return r;
}
__device__ __forceinline__ void mma8(float* c, const uint32_t* a,
                                     uint32_t b0, uint32_t b1) {
    asm volatile(
        "mma.sync.aligned.m16n8k8.row.col.f32.tf32.tf32.f32 "
        "{%0,%1,%2,%3},{%4,%5,%6,%7},{%8,%9},{%0,%1,%2,%3};"
        : "+f"(c[0]), "+f"(c[1]), "+f"(c[2]), "+f"(c[3])
        : "r"(a[0]), "r"(a[1]), "r"(a[2]), "r"(a[3]), "r"(b0), "r"(b1));
}
__device__ __forceinline__ uint32_t smem_u32(const void* p) {
    uint32_t a;
    asm("{ .reg .u64 t; cvta.to.shared.u64 t, %1; cvt.u32.u64 %0, t; }" : "=r"(a) : "l"(p));
    return a;
}
__device__ __forceinline__ void cp16(uint32_t s, const void* g) {
    asm volatile("cp.async.cg.shared.global [%0], [%1], 16;" :: "r"(s), "l"(g));
}
#define CP_COMMIT() asm volatile("cp.async.commit_group;" ::: "memory")
#define CP_WAIT2()  asm volatile("cp.async.wait_group 2;" ::: "memory")
#define CP_WAIT0()  asm volatile("cp.async.wait_group 0;" ::: "memory")
__device__ __forceinline__ float lds32(uint32_t a) {
    float v; asm volatile("ld.shared.f32 %0, [%1];" : "=f"(v) : "r"(a)); return v;
}
__device__ __forceinline__ float4 lds128(uint32_t a) {
    float4 v;
    asm volatile("ld.shared.v4.f32 {%0,%1,%2,%3}, [%4];"
                 : "=f"(v.x), "=f"(v.y), "=f"(v.z), "=f"(v.w) : "r"(a));
    return v;
}

// packed f32x2 helpers
__device__ __forceinline__ ull pack2(float lo, float hi) {
    ull r; asm("mov.b64 %0, {%1, %2};" : "=l"(r) : "f"(lo), "f"(hi)); return r;
}
__device__ __forceinline__ void fma2(ull& d, ull a, ull b) {
    asm("fma.rn.f32x2 %0, %1, %2, %0;" : "+l"(d) : "l"(a), "l"(b));
}
__device__ __forceinline__ ull add2(ull a, ull b) {
    ull r; asm("add.rn.f32x2 %0, %1, %2;" : "=l"(r) : "l"(a), "l"(b)); return r;
}
__device__ __forceinline__ ull neg2(ull a) {
    return a ^ 0x8000000080000000ull;
}
__device__ __forceinline__ float2 unpk(ull v) {
    float2 f; asm("mov.b64 {%0, %1}, %2;" : "=f"(f.x), "=f"(f.y) : "l"(v)); return f;
}

// ---------------- kernel 1: dir column norms + accumulator zeroing ---------
// 64 blocks x 256 threads, coalesced over dirs rows (R11-proven shape).
__global__ __launch_bounds__(256) void k_dirnorm(const float* __restrict__ dirs) {
    __shared__ float red[4][64];
    const int tid = threadIdx.x;
    const int gidx = blockIdx.x * 256 + tid;

    // zeroing folded in (coalesced, spread across blocks)
    if (gidx < ND)      { g_colsum[gidx] = 0.f; g_colsq[gidx] = 0.f; }
    if (gidx < NS)      { g_psum[gidx]   = 0.f; g_psq[gidx]   = 0.f; g_norm2[gidx] = 0.f; }
    if (gidx >= 1024 && gidx < 1024 + NT * NS) {
        g_ecfr[gidx - 1024] = 0.f; g_ecfi[gidx - 1024] = 0.f;
    }
    if (gidx == 0) g_done = 0;

    int s = tid & 63, dq = tid >> 6;
    int d0 = blockIdx.x * 12;
    float acc = 0.f;
    #pragma unroll
    for (int j = 0; j < 3; j++) {
        float v = dirs[(size_t)(d0 + j * 4 + dq) * NS + s];
        acc += v * v;
    }
    red[dq][s] = acc;
    __syncthreads();
    if (tid < 64) {
        float v = red[0][s] + red[1][s] + red[2][s] + red[3][s];
        atomicAdd(&g_norm2[s], v);
    }
}

// ---------------- kernel 1b: build tf32 A fragments ------------------------
__global__ void k_prepfrag(const float* __restrict__ dirs) {
    int idx = blockIdx.x * blockDim.x + threadIdx.x;   // 48*256 = 12288
    int kk = idx >> 7, rem = idx & 127;
    int mt = rem >> 5, lane = rem & 31;
    int g = lane >> 2, t = lane & 3;
    int s0 = mt * 16 + g;
    int k0 = kk * 8 + t;
    float i0 = 1.0f / sqrtf(g_norm2[s0]);
    float i1 = 1.0f / sqrtf(g_norm2[s0 + 8]);
    float4 v;
    v.x = __uint_as_float(f2tf(dirs[(size_t)k0 * NS + s0]       * i0));
    v.y = __uint_as_float(f2tf(dirs[(size_t)k0 * NS + s0 + 8]   * i1));
    v.z = __uint_as_float(f2tf(dirs[(size_t)(k0 + 4) * NS + s0]     * i0));
    v.w = __uint_as_float(f2tf(dirs[(size_t)(k0 + 4) * NS + s0 + 8] * i1));
    g_dirsFrag[idx] = v;
}

// ---------------- kernel 2: staged HMMA tf32 GEMM + colstats + psums -------
// (bit-identical mainloop to the proven 51.6us R11 version)
#define ZRING (8 * 2 * 4096)          // 64 KB
#define FROFF ZRING
#define SMTOT (ZRING + 3 * 8192)      // 88 KB dynamic

__global__ __launch_bounds__(256, 2) void k_gemm(const float* __restrict__ z) {
    extern __shared__ __align__(128) char smem[];
    __shared__ float scol_s[ND], scol_q[ND];
    __shared__ float ssum[64], ssq[64];

    const uint32_t sb = smem_u32(smem);
    const uint32_t fb = sb + FROFF;
    const int tid = threadIdx.x;
    const int wid = tid >> 5, lane = tid & 31;
    const int g = lane >> 2, t = lane & 3;
    const int nwarp = blockIdx.x * 256 + wid * 32;

    for (int i = tid; i < ND; i += 256) { scol_s[i] = 0.f; scol_q[i] = 0.f; }
    if (tid < 64) { ssum[tid] = 0.f; ssq[tid] = 0.f; }
    __syncthreads();

    const uint32_t wstage = sb + wid * 8192;
    const int fr = lane >> 3, fu = lane & 7;
    const float* zsrc = z + (size_t)nwarp * ND;

    #define FILL_Z(ch) do { \
        uint32_t dst = wstage + ((ch) & 1) * 4096; \
        const float* srcb = zsrc + (ch) * 32; \
        _Pragma("unroll") \
        for (int i = 0; i < 8; i++) { \
            int r = i * 4 + fr; \
            cp16(dst + r * 128 + ((fu ^ (r & 7)) << 4), \
                 srcb + (size_t)r * ND + fu * 4); \
        } \
        CP_COMMIT(); \
    } while (0)

    #define FILL_F(ch) do { \
        uint32_t dst = fb + ((ch) % 3) * 8192 + tid * 32; \
        const float4* srcb = g_dirsFrag + (ch) * 512 + tid * 2; \
        cp16(dst,      srcb); \
        cp16(dst + 16, srcb + 1); \
        CP_COMMIT(); \
    } while (0)

    FILL_F(0); FILL_Z(0); FILL_F(1); FILL_Z(1);

    float c[4][4][4];
    #pragma unroll
    for (int mt = 0; mt < 4; mt++)
        #pragma unroll
        for (int nt = 0; nt < 4; nt++)
            #pragma unroll
            for (int r = 0; r < 4; r++) c[mt][nt][r] = 0.f;

    for (int ch = 0; ch < NCH; ch++) {
        if (ch < NCH - 1) { CP_WAIT2(); } else { CP_WAIT0(); }
        __syncthreads();

        if (ch + 2 < NCH) FILL_F(ch + 2);

        const uint32_t zstage = wstage + (ch & 1) * 4096;
        const uint32_t fstage = fb + (ch % 3) * 8192;

        #pragma unroll
        for (int kk = 0; kk < 4; kk++) {
            uint32_t a[4][4];
            #pragma unroll
            for (int mt = 0; mt < 4; mt++) {
                float4 v = lds128(fstage + ((kk * 128 + mt * 32 + lane) << 4));
                a[mt][0] = __float_as_uint(v.x);
                a[mt][1] = __float_as_uint(v.y);
                a[mt][2] = __float_as_uint(v.z);
                a[mt][3] = __float_as_uint(v.w);
            }
            uint32_t b0[4], b1[4];
            #pragma unroll
            for (int nt = 0; nt < 4; nt++) {
                int row = nt * 8 + g;
                uint32_t base = zstage + row * 128 + t * 4;
                b0[nt] = __float_as_uint(lds32(base + (((2 * kk)     ^ g) << 4)));
                b1[nt] = __float_as_uint(lds32(base + (((2 * kk + 1) ^ g) << 4)));
            }
            #pragma unroll
            for (int mt = 0; mt < 4; mt++)
                #pragma unroll
                for (int nt = 0; nt < 4; nt++)
                    mma8(c[mt][nt], a[mt], b0[nt], b1[nt]);
        }

        {
            const int cu = lane >> 2, co = (lane & 3) * 4;
            float cs = 0.f, cq = 0.f;
            #pragma unroll
            for (int r = 0; r < 32; r++) {
                float v = lds32(zstage + r * 128 + ((cu ^ (r & 7)) << 4) + co);
                cs += v; cq += v * v;
            }
            atomicAdd(&scol_s[ch * 32 + lane], cs);
            atomicAdd(&scol_q[ch * 32 + lane], cq);
        }

        if (ch + 2 < NCH) FILL_Z(ch + 2);
    }

    #pragma unroll
    for (int mt = 0; mt < 4; mt++) {
        float su0 = 0.f, su1 = 0.f, sq0 = 0.f, sq1 = 0.f;
        int s0 = mt * 16 + g;
        #pragma unroll
        for (int nt = 0; nt < 4; nt++) {
            float d0 = c[mt][nt][0], d1 = c[mt][nt][1];
            float d2 = c[mt][nt][2], d3 = c[mt][nt][3];
            int n = nwarp + nt * 8 + t * 2;
            *(float2*)(g_projT + (size_t)s0 * NB + n)       = make_float2(d0, d1);
            *(float2*)(g_projT + (size_t)(s0 + 8) * NB + n) = make_float2(d2, d3);
            su0 += d0 + d1; sq0 += d0 * d0 + d1 * d1;
            su1 += d2 + d3; sq1 += d2 * d2 + d3 * d3;
        }
        #pragma unroll
        for (int off = 1; off < 4; off <<= 1) {
            su0 += __shfl_xor_sync(0xffffffffu, su0, off);
            sq0 += __shfl_xor_sync(0xffffffffu, sq0, off);
            su1 += __shfl_xor_sync(0xffffffffu, su1, off);
            sq1 += __shfl_xor_sync(0xffffffffu, sq1, off);
        }
        if (t == 0) {
            atomicAdd(&ssum[s0], su0);     atomicAdd(&ssq[s0], sq0);
            atomicAdd(&ssum[s0 + 8], su1); atomicAdd(&ssq[s0 + 8], sq1);
        }
    }
    __syncthreads();
    if (tid < 64) {
        atomicAdd(&g_psum[tid], ssum[tid]);
        atomicAdd(&g_psq[tid],  ssq[tid]);
    }
    #pragma unroll
    for (int rep = 0; rep < 3; rep++) {
        int col = rep * 256 + tid;
        atomicAdd(&g_colsum[col], scol_s[col]);
        atomicAdd(&g_colsq[col],  scol_q[col]);
    }
}

// ---------------- kernel 3: ECF (Chebyshev f32x2) + fused final loss -------
__global__ __launch_bounds__(256) void k_ecf(float* __restrict__ out) {
    __shared__ float red[256];
    __shared__ int slast;
    int s = blockIdx.y;
    float pmean = g_psum[s] / (float)NB;
    float pvar = (g_psq[s] - (float)NB * pmean * pmean) / (float)(NB - 1);
    float invstd = 1.0f / (sqrtf(fmaxf(pvar, 0.f)) + EPSV);

    size_t basep = (size_t)s * NB + blockIdx.x * 4096;
    const float2* src = (const float2*)(g_projT + basep);

    ull CR[NT], CI[NT];
    #pragma unroll
    for (int j = 0; j < NT; j++) { CR[j] = 0ull; CI[j] = 0ull; }

    #pragma unroll 2
    for (int i = 0; i < 8; i++) {
        float2 pv = src[threadIdx.x + i * 256];
        float p0 = (pv.x - pmean) * invstd;
        float p1 = (pv.y - pmean) * invstd;
        float c0, s0, c1v, s1v;
        __sincosf(DT * p0, &s0, &c0);
        __sincosf(DT * p1, &s1v, &c1v);
        ull cc = pack2(c0, c1v);
        ull ss = pack2(s0, s1v);
        ull twoc = add2(cc, cc);
        ull ncp = pack2(-1.f, -1.f);
        ull nsp = 0ull;
        #pragma unroll
        for (int j = 0; j < NT; j++) {
            CR[j] = add2(CR[j], cc);
            CI[j] = add2(CI[j], ss);
            ull cn = ncp; fma2(cn, twoc, cc);
            ull sn = nsp; fma2(sn, twoc, ss);
            ncp = neg2(cc); nsp = neg2(ss);
            cc = cn; ss = sn;
        }
    }

    unsigned msk = 0xffffffffu;
    #pragma unroll
    for (int j = 0; j < NT; j++) {
        float2 r2 = unpk(CR[j]);
        float2 i2 = unpk(CI[j]);
        float r = r2.x + r2.y, im = i2.x + i2.y;
        #pragma unroll
        for (int off = 16; off; off >>= 1) {
            r  += __shfl_down_sync(msk, r,  off);
            im += __shfl_down_sync(msk, im, off);
        }
        if ((threadIdx.x & 31) == 0) {
            atomicAdd(&g_ecfr[j * NS + s], r);
            atomicAdd(&g_ecfi[j * NS + s], im);
        }
    }

    // completion protocol: fence own atomics, count blocks, last block finishes
    if ((threadIdx.x & 31) == 0) __threadfence();
    __syncthreads();
    if (threadIdx.x == 0) {
        unsigned r = atomicAdd(&g_done, 1u);
        slast = (r == ECF_BLOCKS - 1);
    }
    __syncthreads();
    if (!slast) return;
    __threadfence();   // acquire side

    int t = threadIdx.x;
    float acc = 0.f;
    for (int d = t; d < ND; d += 256) {
        float mean = g_colsum[d] / (float)NB;
        float var = (g_colsq[d] - (float)NB * mean * mean) / (float)(NB - 1);
        float stdv = sqrtf(fmaxf(var, 0.f));
        acc += fmaxf(1.0f - stdv, 0.f) * (1.0f / (float)ND);
    }
    for (int idx = t; idx < NT * NS; idx += 256) {
        int j = idx / NS;
        float tj = DT * (float)(j + 1);
        float er = g_ecfr[idx] / (float)NB;
        float ei = g_ecfi[idx] / (float)NB;
        float tcf = expf(-0.5f * tj * tj);
        float term = er * er + ei * ei - 2.0f * er * tcf + tcf * tcf;
        float w = DT * ((j == 0 || j == NT - 1) ? 0.5f : 1.0f);
        acc += w * term * (1.0f / (float)NS);
    }
    red[t] = acc;
    __syncthreads();
    for (int off = 128; off; off >>= 1) {
        if (t < off) red[t] += red[t + off];
        __syncthreads();
    }
    if (t == 0) out[0] = red[0];
}

// ---------------- launch -----------------------------------------------------
extern "C" void kernel_launch(void* const* d_in, const int* in_sizes, int n_in,
                              void* d_out, int out_size) {
    const float* z    = (const float*)d_in[0];   // [65536, 768]
    const float* dirs = (const float*)d_in[1];   // [768, 64]
    float* out = (float*)d_out;

    cudaFuncSetAttribute(k_gemm, cudaFuncAttributeMaxDynamicSharedMemorySize, SMTOT);

    k_dirnorm<<<64, 256>>>(dirs);
    k_prepfrag<<<48, 256>>>(dirs);
    k_gemm<<<NB / 256, 256, SMTOT>>>(z);
    k_ecf<<<dim3(16, NS), 256>>>(out);
}

// round 14
// speedup vs baseline: 1.2208x; 1.1049x over previous
#include <cuda_runtime.h>
#include <math.h>
#include <stdint.h>

#define NB 65536
#define ND 768
#define NS 64
#define NT 17
#define T_MAX 2.0f
#define DT (T_MAX / (float)NT)
#define EPSV 1e-8f
#define NCH 24                 // k chunks of 32
#define NKK (ND / 8)           // 96

typedef unsigned long long ull;

// ---------------- device scratch ----------------
__device__ float  g_projT[NS * NB];
__device__ float4 g_dirsFrag[NKK * 4 * 32];
__device__ float  g_norm2[NS];
__device__ float  g_colsum[ND];
__device__ float  g_colsq[ND];
__device__ float  g_psum[NS];
__device__ float  g_psq[NS];
__device__ float  g_ecfr[NT * NS];
__device__ float  g_ecfi[NT * NS];

// ---------------- ptx helpers ----------------
__device__ __forceinline__ uint32_t f2tf(float f) {
    uint32_t r; asm("cvt.rna.tf32.f32 %0, %1;" : "=r"(r) : "f"(f)); return r;
}
__device__ __forceinline__ void mma8(float* c, const uint32_t* a,
                                     uint32_t b0, uint32_t b1) {
    asm volatile(
        "mma.sync.aligned.m16n8k8.row.col.f32.tf32.tf32.f32 "
        "{%0,%1,%2,%3},{%4,%5,%6,%7},{%8,%9},{%0,%1,%2,%3};"
        : "+f"(c[0]), "+f"(c[1]), "+f"(c[2]), "+f"(c[3])
        : "r"(a[0]), "r"(a[1]), "r"(a[2]), "r"(a[3]), "r"(b0), "r"(b1));
}
__device__ __forceinline__ uint32_t smem_u32(const void* p) {
    uint32_t a;
    asm("{ .reg .u64 t; cvta.to.shared.u64 t, %1; cvt.u32.u64 %0, t; }" : "=r"(a) : "l"(p));
    return a;
}
__device__ __forceinline__ void cp16(uint32_t s, const void* g) {
    asm volatile("cp.async.cg.shared.global [%0], [%1], 16;" :: "r"(s), "l"(g));
}
#define CP_COMMIT() asm volatile("cp.async.commit_group;" ::: "memory")
#define CP_WAIT2()  asm volatile("cp.async.wait_group 2;" ::: "memory")
#define CP_WAIT0()  asm volatile("cp.async.wait_group 0;" ::: "memory")
__device__ __forceinline__ float lds32(uint32_t a) {
    float v; asm volatile("ld.shared.f32 %0, [%1];" : "=f"(v) : "r"(a)); return v;
}
__device__ __forceinline__ float4 lds128(uint32_t a) {
    float4 v;
    asm volatile("ld.shared.v4.f32 {%0,%1,%2,%3}, [%4];"
                 : "=f"(v.x), "=f"(v.y), "=f"(v.z), "=f"(v.w) : "r"(a));
    return v;
}

// packed f32x2 helpers
__device__ __forceinline__ ull pack2(float lo, float hi) {
    ull r; asm("mov.b64 %0, {%1, %2};" : "=l"(r) : "f"(lo), "f"(hi)); return r;
}
__device__ __forceinline__ void fma2(ull& d, ull a, ull b) {
    asm("fma.rn.f32x2 %0, %1, %2, %0;" : "+l"(d) : "l"(a), "l"(b));
}
__device__ __forceinline__ ull mul2(ull a, ull b) {
    ull r; asm("mul.rn.f32x2 %0, %1, %2;" : "=l"(r) : "l"(a), "l"(b)); return r;
}
__device__ __forceinline__ ull add2(ull a, ull b) {
    ull r; asm("add.rn.f32x2 %0, %1, %2;" : "=l"(r) : "l"(a), "l"(b)); return r;
}
__device__ __forceinline__ ull neg2(ull a) {
    return a ^ 0x8000000080000000ull;
}
__device__ __forceinline__ float2 unpk(ull v) {
    float2 f; asm("mov.b64 {%0, %1}, %2;" : "=f"(f.x), "=f"(f.y) : "l"(v)); return f;
}

// ---------------- kernel 0: zero accumulators (graph replayed) -------------
__global__ void k_init() {
    int i = blockIdx.x * blockDim.x + threadIdx.x;
    if (i < ND)      { g_colsum[i] = 0.f; g_colsq[i] = 0.f; }
    if (i < NS)      { g_psum[i]   = 0.f; g_psq[i]   = 0.f; g_norm2[i] = 0.f; }
    if (i < NT * NS) { g_ecfr[i]   = 0.f; g_ecfi[i]  = 0.f; }
}

// ---------------- kernel 1: dir column norms (parallel, coalesced) --------
__global__ __launch_bounds__(256) void k_dirnorm(const float* __restrict__ dirs) {
    __shared__ float red[4][64];
    int s = threadIdx.x & 63, dq = threadIdx.x >> 6;
    int d0 = blockIdx.x * 12;
    float acc = 0.f;
    #pragma unroll
    for (int j = 0; j < 3; j++) {
        float v = dirs[(size_t)(d0 + j * 4 + dq) * NS + s];
        acc += v * v;
    }
    red[dq][s] = acc;
    __syncthreads();
    if (threadIdx.x < 64) {
        float v = red[0][s] + red[1][s] + red[2][s] + red[3][s];
        atomicAdd(&g_norm2[s], v);
    }
}

// ---------------- kernel 1b: build tf32 A fragments ------------------------
__global__ void k_prepfrag(const float* __restrict__ dirs) {
    int idx = blockIdx.x * blockDim.x + threadIdx.x;   // 48*256 = 12288
    int kk = idx >> 7, rem = idx & 127;
    int mt = rem >> 5, lane = rem & 31;
    int g = lane >> 2, t = lane & 3;
    int s0 = mt * 16 + g;
    int k0 = kk * 8 + t;
    float i0 = 1.0f / sqrtf(g_norm2[s0]);
    float i1 = 1.0f / sqrtf(g_norm2[s0 + 8]);
    float4 v;
    v.x = __uint_as_float(f2tf(dirs[(size_t)k0 * NS + s0]       * i0));
    v.y = __uint_as_float(f2tf(dirs[(size_t)k0 * NS + s0 + 8]   * i1));
    v.z = __uint_as_float(f2tf(dirs[(size_t)(k0 + 4) * NS + s0]     * i0));
    v.w = __uint_as_float(f2tf(dirs[(size_t)(k0 + 4) * NS + s0 + 8] * i1));
    g_dirsFrag[idx] = v;
}

// ---------------- kernel 2: staged HMMA tf32 GEMM + colstats + psums -------
// (bit-identical to the proven 51.6us R11 version)
#define ZRING (8 * 2 * 4096)          // 64 KB
#define FROFF ZRING
#define SMTOT (ZRING + 3 * 8192)      // 88 KB dynamic

__global__ __launch_bounds__(256, 2) void k_gemm(const float* __restrict__ z) {
    extern __shared__ __align__(128) char smem[];
    __shared__ float scol_s[ND], scol_q[ND];
    __shared__ float ssum[64], ssq[64];

    const uint32_t sb = smem_u32(smem);
    const uint32_t fb = sb + FROFF;
    const int tid = threadIdx.x;
    const int wid = tid >> 5, lane = tid & 31;
    const int g = lane >> 2, t = lane & 3;
    const int nwarp = blockIdx.x * 256 + wid * 32;

    for (int i = tid; i < ND; i += 256) { scol_s[i] = 0.f; scol_q[i] = 0.f; }
    if (tid < 64) { ssum[tid] = 0.f; ssq[tid] = 0.f; }
    __syncthreads();

    const uint32_t wstage = sb + wid * 8192;
    const int fr = lane >> 3, fu = lane & 7;
    const float* zsrc = z + (size_t)nwarp * ND;

    #define FILL_Z(ch) do { \
        uint32_t dst = wstage + ((ch) & 1) * 4096; \
        const float* srcb = zsrc + (ch) * 32; \
        _Pragma("unroll") \
        for (int i = 0; i < 8; i++) { \
            int r = i * 4 + fr; \
            cp16(dst + r * 128 + ((fu ^ (r & 7)) << 4), \
                 srcb + (size_t)r * ND + fu * 4); \
        } \
        CP_COMMIT(); \
    } while (0)

    #define FILL_F(ch) do { \
        uint32_t dst = fb + ((ch) % 3) * 8192 + tid * 32; \
        const float4* srcb = g_dirsFrag + (ch) * 512 + tid * 2; \
        cp16(dst,      srcb); \
        cp16(dst + 16, srcb + 1); \
        CP_COMMIT(); \
    } while (0)

    FILL_F(0); FILL_Z(0); FILL_F(1); FILL_Z(1);

    float c[4][4][4];
    #pragma unroll
    for (int mt = 0; mt < 4; mt++)
        #pragma unroll
        for (int nt = 0; nt < 4; nt++)
            #pragma unroll
            for (int r = 0; r < 4; r++) c[mt][nt][r] = 0.f;

    for (int ch = 0; ch < NCH; ch++) {
        if (ch < NCH - 1) { CP_WAIT2(); } else { CP_WAIT0(); }
        __syncthreads();

        if (ch + 2 < NCH) FILL_F(ch + 2);

        const uint32_t zstage = wstage + (ch & 1) * 4096;
        const uint32_t fstage = fb + (ch % 3) * 8192;

        #pragma unroll
        for (int kk = 0; kk < 4; kk++) {
            uint32_t a[4][4];
            #pragma unroll
            for (int mt = 0; mt < 4; mt++) {
                float4 v = lds128(fstage + ((kk * 128 + mt * 32 + lane) << 4));
                a[mt][0] = __float_as_uint(v.x);
                a[mt][1] = __float_as_uint(v.y);
                a[mt][2] = __float_as_uint(v.z);
                a[mt][3] = __float_as_uint(v.w);
            }
            uint32_t b0[4], b1[4];
            #pragma unroll
            for (int nt = 0; nt < 4; nt++) {
                int row = nt * 8 + g;
                uint32_t base = zstage + row * 128 + t * 4;
                b0[nt] = __float_as_uint(lds32(base + (((2 * kk)     ^ g) << 4)));
                b1[nt] = __float_as_uint(lds32(base + (((2 * kk + 1) ^ g) << 4)));
            }
            #pragma unroll
            for (int mt = 0; mt < 4; mt++)
                #pragma unroll
                for (int nt = 0; nt < 4; nt++)
                    mma8(c[mt][nt], a[mt], b0[nt], b1[nt]);
        }

        {
            const int cu = lane >> 2, co = (lane & 3) * 4;
            float cs = 0.f, cq = 0.f;
            #pragma unroll
            for (int r = 0; r < 32; r++) {
                float v = lds32(zstage + r * 128 + ((cu ^ (r & 7)) << 4) + co);
                cs += v; cq += v * v;
            }
            atomicAdd(&scol_s[ch * 32 + lane], cs);
            atomicAdd(&scol_q[ch * 32 + lane], cq);
        }

        if (ch + 2 < NCH) FILL_Z(ch + 2);
    }

    #pragma unroll
    for (int mt = 0; mt < 4; mt++) {
        float su0 = 0.f, su1 = 0.f, sq0 = 0.f, sq1 = 0.f;
        int s0 = mt * 16 + g;
        #pragma unroll
        for (int nt = 0; nt < 4; nt++) {
            float d0 = c[mt][nt][0], d1 = c[mt][nt][1];
            float d2 = c[mt][nt][2], d3 = c[mt][nt][3];
            int n = nwarp + nt * 8 + t * 2;
            *(float2*)(g_projT + (size_t)s0 * NB + n)       = make_float2(d0, d1);
            *(float2*)(g_projT + (size_t)(s0 + 8) * NB + n) = make_float2(d2, d3);
            su0 += d0 + d1; sq0 += d0 * d0 + d1 * d1;
            su1 += d2 + d3; sq1 += d2 * d2 + d3 * d3;
        }
        #pragma unroll
        for (int off = 1; off < 4; off <<= 1) {
            su0 += __shfl_xor_sync(0xffffffffu, su0, off);
            sq0 += __shfl_xor_sync(0xffffffffu, sq0, off);
            su1 += __shfl_xor_sync(0xffffffffu, su1, off);
            sq1 += __shfl_xor_sync(0xffffffffu, sq1, off);
        }
        if (t == 0) {
            atomicAdd(&ssum[s0], su0);     atomicAdd(&ssq[s0], sq0);
            atomicAdd(&ssum[s0 + 8], su1); atomicAdd(&ssq[s0 + 8], sq1);
        }
    }
    __syncthreads();
    if (tid < 64) {
        atomicAdd(&g_psum[tid], ssum[tid]);
        atomicAdd(&g_psq[tid],  ssq[tid]);
    }
    #pragma unroll
    for (int rep = 0; rep < 3; rep++) {
        int col = rep * 256 + tid;
        atomicAdd(&g_colsum[col], scol_s[col]);
        atomicAdd(&g_colsq[col],  scol_q[col]);
    }
}

// ---------------- kernel 6: ECF split over j-halves ------------------------
// blockIdx.z = 0: multiples 1..9  (Chebyshev from cos(theta))
// blockIdx.z = 1: multiples 10..17 (start cos(9th),cos(10th) via sincos+angle-add)
// Half the accumulators per block -> lower regs, higher occupancy, shorter chain.
__global__ __launch_bounds__(256) void k_ecf() {
    int s = blockIdx.y;
    float pmean = g_psum[s] / (float)NB;
    float pvar = (g_psq[s] - (float)NB * pmean * pmean) / (float)(NB - 1);
    float invstd = 1.0f / (sqrtf(fmaxf(pvar, 0.f)) + EPSV);

    size_t basep = (size_t)s * NB + blockIdx.x * 4096;
    const float2* src = (const float2*)(g_projT + basep);
    unsigned msk = 0xffffffffu;

    if (blockIdx.z == 0) {
        ull CR[9], CI[9];
        #pragma unroll
        for (int j = 0; j < 9; j++) { CR[j] = 0ull; CI[j] = 0ull; }

        #pragma unroll 2
        for (int i = 0; i < 8; i++) {
            float2 pv = src[threadIdx.x + i * 256];
            float p0 = (pv.x - pmean) * invstd;
            float p1 = (pv.y - pmean) * invstd;
            float c0, s0, c1v, s1v;
            __sincosf(DT * p0, &s0, &c0);
            __sincosf(DT * p1, &s1v, &c1v);
            ull cc = pack2(c0, c1v);
            ull ss = pack2(s0, s1v);
            ull twoc = add2(cc, cc);
            ull ncp = pack2(-1.f, -1.f);
            ull nsp = 0ull;
            #pragma unroll
            for (int j = 0; j < 9; j++) {
                CR[j] = add2(CR[j], cc);
                CI[j] = add2(CI[j], ss);
                ull cn = ncp; fma2(cn, twoc, cc);
                ull sn = nsp; fma2(sn, twoc, ss);
                ncp = neg2(cc); nsp = neg2(ss);
                cc = cn; ss = sn;
            }
        }
        #pragma unroll
        for (int j = 0; j < 9; j++) {
            float2 r2 = unpk(CR[j]);
            float2 i2 = unpk(CI[j]);
            float r = r2.x + r2.y, im = i2.x + i2.y;
            #pragma unroll
            for (int off = 16; off; off >>= 1) {
                r  += __shfl_down_sync(msk, r,  off);
                im += __shfl_down_sync(msk, im, off);
            }
            if ((threadIdx.x & 31) == 0) {
                atomicAdd(&g_ecfr[j * NS + s], r);
                atomicAdd(&g_ecfi[j * NS + s], im);
            }
        }
    } else {
        ull CR[8], CI[8];
        #pragma unroll
        for (int j = 0; j < 8; j++) { CR[j] = 0ull; CI[j] = 0ull; }

        #pragma unroll 2
        for (int i = 0; i < 8; i++) {
            float2 pv = src[threadIdx.x + i * 256];
            float p0 = (pv.x - pmean) * invstd;
            float p1 = (pv.y - pmean) * invstd;
            float c0, s0, c1v, s1v, c90, s90, c91, s91;
            __sincosf(DT * p0, &s0, &c0);
            __sincosf(DT * p1, &s1v, &c1v);
            __sincosf(9.f * DT * p0, &s90, &c90);
            __sincosf(9.f * DT * p1, &s91, &c91);
            ull c1p = pack2(c0, c1v);
            ull s1p = pack2(s0, s1v);
            ull c9p = pack2(c90, c91);
            ull s9p = pack2(s90, s91);
            ull twoc = add2(c1p, c1p);
            // cos(10) = c9*c1 - s9*s1 ; sin(10) = s9*c1 + c9*s1
            ull cc = mul2(c9p, c1p); fma2(cc, s9p, neg2(s1p));
            ull ss = mul2(s9p, c1p); fma2(ss, c9p, s1p);
            ull ncp = neg2(c9p);
            ull nsp = neg2(s9p);
            #pragma unroll
            for (int j = 0; j < 8; j++) {       // multiples 10..17
                CR[j] = add2(CR[j], cc);
                CI[j] = add2(CI[j], ss);
                ull cn = ncp; fma2(cn, twoc, cc);
                ull sn = nsp; fma2(sn, twoc, ss);
                ncp = neg2(cc); nsp = neg2(ss);
                cc = cn; ss = sn;
            }
        }
        #pragma unroll
        for (int j = 0; j < 8; j++) {
            float2 r2 = unpk(CR[j]);
            float2 i2 = unpk(CI[j]);
            float r = r2.x + r2.y, im = i2.x + i2.y;
            #pragma unroll
            for (int off = 16; off; off >>= 1) {
                r  += __shfl_down_sync(msk, r,  off);
                im += __shfl_down_sync(msk, im, off);
            }
            if ((threadIdx.x & 31) == 0) {
                atomicAdd(&g_ecfr[(9 + j) * NS + s], r);
                atomicAdd(&g_ecfi[(9 + j) * NS + s], im);
            }
        }
    }
}

// ---------------- kernel 7: final scalar loss -------------------------------
__global__ __launch_bounds__(256) void k_final(float* __restrict__ out) {
    __shared__ float red[256];
    int t = threadIdx.x;
    float acc = 0.f;

    for (int d = t; d < ND; d += 256) {
        float mean = g_colsum[d] / (float)NB;
        float var = (g_colsq[d] - (float)NB * mean * mean) / (float)(NB - 1);
        float stdv = sqrtf(fmaxf(var, 0.f));
        acc += fmaxf(1.0f - stdv, 0.f) * (1.0f / (float)ND);
    }

    for (int idx = t; idx < NT * NS; idx += 256) {
        int j = idx / NS;
        float tj = DT * (float)(j + 1);
        float er = g_ecfr[idx] / (float)NB;
        float ei = g_ecfi[idx] / (float)NB;
        float tcf = expf(-0.5f * tj * tj);
        float term = er * er + ei * ei - 2.0f * er * tcf + tcf * tcf;
        float w = DT * ((j == 0 || j == NT - 1) ? 0.5f : 1.0f);
        acc += w * term * (1.0f / (float)NS);
    }

    red[t] = acc;
    __syncthreads();
    for (int off = 128; off; off >>= 1) {
        if (t < off) red[t] += red[t + off];
        __syncthreads();
    }
    if (t == 0) out[0] = red[0];
}

// ---------------- launch -----------------------------------------------------
extern "C" void kernel_launch(void* const* d_in, const int* in_sizes, int n_in,
                              void* d_out, int out_size) {
    const float* z    = (const float*)d_in[0];   // [65536, 768]
    const float* dirs = (const float*)d_in[1];   // [768, 64]
    float* out = (float*)d_out;

    cudaFuncSetAttribute(k_gemm, cudaFuncAttributeMaxDynamicSharedMemorySize, SMTOT);

    k_init<<<5, 256>>>();
    k_dirnorm<<<64, 256>>>(dirs);
    k_prepfrag<<<48, 256>>>(dirs);
    k_gemm<<<NB / 256, 256, SMTOT>>>(z);
    k_ecf<<<dim3(16, NS, 2), 256>>>();
    k_final<<<1, 256>>>(out);
}

// round 15
// speedup vs baseline: 1.2307x; 1.0082x over previous
#include <cuda_runtime.h>
#include <math.h>
#include <stdint.h>

#define NB 65536
#define ND 768
#define NS 64
#define NT 17
#define T_MAX 2.0f
#define DT (T_MAX / (float)NT)
#define EPSV 1e-8f
#define NCH 24                 // k chunks of 32
#define NKK (ND / 8)           // 96

typedef unsigned long long ull;

// ---------------- device scratch ----------------
__device__ float  g_projT[NS * NB];
__device__ float4 g_dirsFrag[NKK * 4 * 32];
__device__ float  g_norm2[NS];
__device__ float  g_colsum[ND];
__device__ float  g_colsq[ND];
__device__ float  g_psum[NS];
__device__ float  g_psq[NS];
__device__ float  g_ecfr[NT * NS];
__device__ float  g_ecfi[NT * NS];

// ---------------- ptx helpers ----------------
__device__ __forceinline__ uint32_t f2tf(float f) {
    uint32_t r; asm("cvt.rna.tf32.f32 %0, %1;" : "=r"(r) : "f"(f)); return r;
}
__device__ __forceinline__ void mma8(float* c, const uint32_t* a,
                                     uint32_t b0, uint32_t b1) {
    asm volatile(
        "mma.sync.aligned.m16n8k8.row.col.f32.tf32.tf32.f32 "
        "{%0,%1,%2,%3},{%4,%5,%6,%7},{%8,%9},{%0,%1,%2,%3};"
        : "+f"(c[0]), "+f"(c[1]), "+f"(c[2]), "+f"(c[3])
        : "r"(a[0]), "r"(a[1]), "r"(a[2]), "r"(a[3]), "r"(b0), "r"(b1));
}
__device__ __forceinline__ uint32_t smem_u32(const void* p) {
    uint32_t a;
    asm("{ .reg .u64 t; cvta.to.shared.u64 t, %1; cvt.u32.u64 %0, t; }" : "=r"(a) : "l"(p));
    return a;
}
__device__ __forceinline__ void cp16(uint32_t s, const void* g) {
    asm volatile("cp.async.cg.shared.global [%0], [%1], 16;" :: "r"(s), "l"(g));
}
#define CP_COMMIT() asm volatile("cp.async.commit_group;" ::: "memory")
#define CP_WAIT2()  asm volatile("cp.async.wait_group 2;" ::: "memory")
#define CP_WAIT0()  asm volatile("cp.async.wait_group 0;" ::: "memory")
__device__ __forceinline__ float lds32(uint32_t a) {
    float v; asm volatile("ld.shared.f32 %0, [%1];" : "=f"(v) : "r"(a)); return v;
}
__device__ __forceinline__ float4 lds128(uint32_t a) {
    float4 v;
    asm volatile("ld.shared.v4.f32 {%0,%1,%2,%3}, [%4];"
                 : "=f"(v.x), "=f"(v.y), "=f"(v.z), "=f"(v.w) : "r"(a));
    return v;
}

// packed f32x2 helpers
__device__ __forceinline__ ull pack2(float lo, float hi) {
    ull r; asm("mov.b64 %0, {%1, %2};" : "=l"(r) : "f"(lo), "f"(hi)); return r;
}
__device__ __forceinline__ void fma2(ull& d, ull a, ull b) {
    asm("fma.rn.f32x2 %0, %1, %2, %0;" : "+l"(d) : "l"(a), "l"(b));
}
__device__ __forceinline__ ull add2(ull a, ull b) {
    ull r; asm("add.rn.f32x2 %0, %1, %2;" : "=l"(r) : "l"(a), "l"(b)); return r;
}
__device__ __forceinline__ ull neg2(ull a) {
    return a ^ 0x8000000080000000ull;
}
__device__ __forceinline__ float2 unpk(ull v) {
    float2 f; asm("mov.b64 {%0, %1}, %2;" : "=f"(f.x), "=f"(f.y) : "l"(v)); return f;
}

// ---------------- kernel 1: dir column norms + accumulator zeroing ---------
// 64 blocks x 256 threads, coalesced (R11 shape); zeroing folded in (R13-proven).
__global__ __launch_bounds__(256) void k_dirnorm(const float* __restrict__ dirs) {
    __shared__ float red[4][64];
    const int tid = threadIdx.x;
    const int gidx = blockIdx.x * 256 + tid;

    if (gidx < ND)      { g_colsum[gidx] = 0.f; g_colsq[gidx] = 0.f; }
    if (gidx < NS)      { g_psum[gidx]   = 0.f; g_psq[gidx]   = 0.f; g_norm2[gidx] = 0.f; }
    if (gidx >= 1024 && gidx < 1024 + NT * NS) {
        g_ecfr[gidx - 1024] = 0.f; g_ecfi[gidx - 1024] = 0.f;
    }

    int s = tid & 63, dq = tid >> 6;
    int d0 = blockIdx.x * 12;
    float acc = 0.f;
    #pragma unroll
    for (int j = 0; j < 3; j++) {
        float v = dirs[(size_t)(d0 + j * 4 + dq) * NS + s];
        acc += v * v;
    }
    red[dq][s] = acc;
    __syncthreads();
    if (tid < 64) {
        float v = red[0][s] + red[1][s] + red[2][s] + red[3][s];
        atomicAdd(&g_norm2[s], v);
    }
}

// ---------------- kernel 1b: build tf32 A fragments ------------------------
__global__ void k_prepfrag(const float* __restrict__ dirs) {
    int idx = blockIdx.x * blockDim.x + threadIdx.x;   // 48*256 = 12288
    int kk = idx >> 7, rem = idx & 127;
    int mt = rem >> 5, lane = rem & 31;
    int g = lane >> 2, t = lane & 3;
    int s0 = mt * 16 + g;
    int k0 = kk * 8 + t;
    float i0 = 1.0f / sqrtf(g_norm2[s0]);
    float i1 = 1.0f / sqrtf(g_norm2[s0 + 8]);
    float4 v;
    v.x = __uint_as_float(f2tf(dirs[(size_t)k0 * NS + s0]       * i0));
    v.y = __uint_as_float(f2tf(dirs[(size_t)k0 * NS + s0 + 8]   * i1));
    v.z = __uint_as_float(f2tf(dirs[(size_t)(k0 + 4) * NS + s0]     * i0));
    v.w = __uint_as_float(f2tf(dirs[(size_t)(k0 + 4) * NS + s0 + 8] * i1));
    g_dirsFrag[idx] = v;
}

// ---------------- kernel 2: staged HMMA tf32 GEMM + colstats + psums -------
// (bit-identical to the proven 51.6us R11 version)
#define ZRING (8 * 2 * 4096)          // 64 KB
#define FROFF ZRING
#define SMTOT (ZRING + 3 * 8192)      // 88 KB dynamic

__global__ __launch_bounds__(256, 2) void k_gemm(const float* __restrict__ z) {
    extern __shared__ __align__(128) char smem[];
    __shared__ float scol_s[ND], scol_q[ND];
    __shared__ float ssum[64], ssq[64];

    const uint32_t sb = smem_u32(smem);
    const uint32_t fb = sb + FROFF;
    const int tid = threadIdx.x;
    const int wid = tid >> 5, lane = tid & 31;
    const int g = lane >> 2, t = lane & 3;
    const int nwarp = blockIdx.x * 256 + wid * 32;

    for (int i = tid; i < ND; i += 256) { scol_s[i] = 0.f; scol_q[i] = 0.f; }
    if (tid < 64) { ssum[tid] = 0.f; ssq[tid] = 0.f; }
    __syncthreads();

    const uint32_t wstage = sb + wid * 8192;
    const int fr = lane >> 3, fu = lane & 7;
    const float* zsrc = z + (size_t)nwarp * ND;

    #define FILL_Z(ch) do { \
        uint32_t dst = wstage + ((ch) & 1) * 4096; \
        const float* srcb = zsrc + (ch) * 32; \
        _Pragma("unroll") \
        for (int i = 0; i < 8; i++) { \
            int r = i * 4 + fr; \
            cp16(dst + r * 128 + ((fu ^ (r & 7)) << 4), \
                 srcb + (size_t)r * ND + fu * 4); \
        } \
        CP_COMMIT(); \
    } while (0)

    #define FILL_F(ch) do { \
        uint32_t dst = fb + ((ch) % 3) * 8192 + tid * 32; \
        const float4* srcb = g_dirsFrag + (ch) * 512 + tid * 2; \
        cp16(dst,      srcb); \
        cp16(dst + 16, srcb + 1); \
        CP_COMMIT(); \
    } while (0)

    FILL_F(0); FILL_Z(0); FILL_F(1); FILL_Z(1);

    float c[4][4][4];
    #pragma unroll
    for (int mt = 0; mt < 4; mt++)
        #pragma unroll
        for (int nt = 0; nt < 4; nt++)
            #pragma unroll
            for (int r = 0; r < 4; r++) c[mt][nt][r] = 0.f;

    for (int ch = 0; ch < NCH; ch++) {
        if (ch < NCH - 1) { CP_WAIT2(); } else { CP_WAIT0(); }
        __syncthreads();

        if (ch + 2 < NCH) FILL_F(ch + 2);

        const uint32_t zstage = wstage + (ch & 1) * 4096;
        const uint32_t fstage = fb + (ch % 3) * 8192;

        #pragma unroll
        for (int kk = 0; kk < 4; kk++) {
            uint32_t a[4][4];
            #pragma unroll
            for (int mt = 0; mt < 4; mt++) {
                float4 v = lds128(fstage + ((kk * 128 + mt * 32 + lane) << 4));
                a[mt][0] = __float_as_uint(v.x);
                a[mt][1] = __float_as_uint(v.y);
                a[mt][2] = __float_as_uint(v.z);
                a[mt][3] = __float_as_uint(v.w);
            }
            uint32_t b0[4], b1[4];
            #pragma unroll
            for (int nt = 0; nt < 4; nt++) {
                int row = nt * 8 + g;
                uint32_t base = zstage + row * 128 + t * 4;
                b0[nt] = __float_as_uint(lds32(base + (((2 * kk)     ^ g) << 4)));
                b1[nt] = __float_as_uint(lds32(base + (((2 * kk + 1) ^ g) << 4)));
            }
            #pragma unroll
            for (int mt = 0; mt < 4; mt++)
                #pragma unroll
                for (int nt = 0; nt < 4; nt++)
                    mma8(c[mt][nt], a[mt], b0[nt], b1[nt]);
        }

        {
            const int cu = lane >> 2, co = (lane & 3) * 4;
            float cs = 0.f, cq = 0.f;
            #pragma unroll
            for (int r = 0; r < 32; r++) {
                float v = lds32(zstage + r * 128 + ((cu ^ (r & 7)) << 4) + co);
                cs += v; cq += v * v;
            }
            atomicAdd(&scol_s[ch * 32 + lane], cs);
            atomicAdd(&scol_q[ch * 32 + lane], cq);
        }

        if (ch + 2 < NCH) FILL_Z(ch + 2);
    }

    #pragma unroll
    for (int mt = 0; mt < 4; mt++) {
        float su0 = 0.f, su1 = 0.f, sq0 = 0.f, sq1 = 0.f;
        int s0 = mt * 16 + g;
        #pragma unroll
        for (int nt = 0; nt < 4; nt++) {
            float d0 = c[mt][nt][0], d1 = c[mt][nt][1];
            float d2 = c[mt][nt][2], d3 = c[mt][nt][3];
            int n = nwarp + nt * 8 + t * 2;
            *(float2*)(g_projT + (size_t)s0 * NB + n)       = make_float2(d0, d1);
            *(float2*)(g_projT + (size_t)(s0 + 8) * NB + n) = make_float2(d2, d3);
            su0 += d0 + d1; sq0 += d0 * d0 + d1 * d1;
            su1 += d2 + d3; sq1 += d2 * d2 + d3 * d3;
        }
        #pragma unroll
        for (int off = 1; off < 4; off <<= 1) {
            su0 += __shfl_xor_sync(0xffffffffu, su0, off);
            sq0 += __shfl_xor_sync(0xffffffffu, sq0, off);
            su1 += __shfl_xor_sync(0xffffffffu, su1, off);
            sq1 += __shfl_xor_sync(0xffffffffu, sq1, off);
        }
        if (t == 0) {
            atomicAdd(&ssum[s0], su0);     atomicAdd(&ssq[s0], sq0);
            atomicAdd(&ssum[s0 + 8], su1); atomicAdd(&ssq[s0 + 8], sq1);
        }
    }
    __syncthreads();
    if (tid < 64) {
        atomicAdd(&g_psum[tid], ssum[tid]);
        atomicAdd(&g_psq[tid],  ssq[tid]);
    }
    #pragma unroll
    for (int rep = 0; rep < 3; rep++) {
        int col = rep * 256 + tid;
        atomicAdd(&g_colsum[col], scol_s[col]);
        atomicAdd(&g_colsq[col],  scol_q[col]);
    }
}

// ---------------- kernel 6: ECF, unsplit, prefetched loads -----------------
__global__ __launch_bounds__(256) void k_ecf() {
    int s = blockIdx.y;
    float pmean = g_psum[s] / (float)NB;
    float pvar = (g_psq[s] - (float)NB * pmean * pmean) / (float)(NB - 1);
    float invstd = 1.0f / (sqrtf(fmaxf(pvar, 0.f)) + EPSV);

    size_t basep = (size_t)s * NB + blockIdx.x * 4096;
    const float2* src = (const float2*)(g_projT + basep);

    // prefetch all 8 loads (MLP 8; L2-resident after GEMM)
    float2 pv[8];
    #pragma unroll
    for (int i = 0; i < 8; i++) pv[i] = src[threadIdx.x + i * 256];

    ull CR[NT], CI[NT];
    #pragma unroll
    for (int j = 0; j < NT; j++) { CR[j] = 0ull; CI[j] = 0ull; }

    #pragma unroll 2
    for (int i = 0; i < 8; i++) {
        float p0 = (pv[i].x - pmean) * invstd;
        float p1 = (pv[i].y - pmean) * invstd;
        float c0, s0, c1v, s1v;
        __sincosf(DT * p0, &s0, &c0);
        __sincosf(DT * p1, &s1v, &c1v);
        ull cc = pack2(c0, c1v);
        ull ss = pack2(s0, s1v);
        ull twoc = add2(cc, cc);
        ull ncp = pack2(-1.f, -1.f);
        ull nsp = 0ull;
        #pragma unroll
        for (int j = 0; j < NT; j++) {
            CR[j] = add2(CR[j], cc);
            CI[j] = add2(CI[j], ss);
            ull cn = ncp; fma2(cn, twoc, cc);
            ull sn = nsp; fma2(sn, twoc, ss);
            ncp = neg2(cc); nsp = neg2(ss);
            cc = cn; ss = sn;
        }
    }

    unsigned msk = 0xffffffffu;
    #pragma unroll
    for (int j = 0; j < NT; j++) {
        float2 r2 = unpk(CR[j]);
        float2 i2 = unpk(CI[j]);
        float r = r2.x + r2.y, im = i2.x + i2.y;
        #pragma unroll
        for (int off = 16; off; off >>= 1) {
            r  += __shfl_down_sync(msk, r,  off);
            im += __shfl_down_sync(msk, im, off);
        }
        if ((threadIdx.x & 31) == 0) {
            atomicAdd(&g_ecfr[j * NS + s], r);
            atomicAdd(&g_ecfi[j * NS + s], im);
        }
    }
}

// ---------------- kernel 7: final scalar loss -------------------------------
__global__ __launch_bounds__(256) void k_final(float* __restrict__ out) {
    __shared__ float red[256];
    int t = threadIdx.x;
    float acc = 0.f;

    for (int d = t; d < ND; d += 256) {
        float mean = g_colsum[d] / (float)NB;
        float var = (g_colsq[d] - (float)NB * mean * mean) / (float)(NB - 1);
        float stdv = sqrtf(fmaxf(var, 0.f));
        acc += fmaxf(1.0f - stdv, 0.f) * (1.0f / (float)ND);
    }

    for (int idx = t; idx < NT * NS; idx += 256) {
        int j = idx / NS;
        float tj = DT * (float)(j + 1);
        float er = g_ecfr[idx] / (float)NB;
        float ei = g_ecfi[idx] / (float)NB;
        float tcf = expf(-0.5f * tj * tj);
        float term = er * er + ei * ei - 2.0f * er * tcf + tcf * tcf;
        float w = DT * ((j == 0 || j == NT - 1) ? 0.5f : 1.0f);
        acc += w * term * (1.0f / (float)NS);
    }

    red[t] = acc;
    __syncthreads();
    for (int off = 128; off; off >>= 1) {
        if (t < off) red[t] += red[t + off];
        __syncthreads();
    }
    if (t == 0) out[0] = red[0];
}

// ---------------- launch -----------------------------------------------------
extern "C" void kernel_launch(void* const* d_in, const int* in_sizes, int n_in,
                              void* d_out, int out_size) {
    const float* z    = (const float*)d_in[0];   // [65536, 768]
    const float* dirs = (const float*)d_in[1];   // [768, 64]
    float* out = (float*)d_out;

    cudaFuncSetAttribute(k_gemm, cudaFuncAttributeMaxDynamicSharedMemorySize, SMTOT);

    k_dirnorm<<<64, 256>>>(dirs);
    k_prepfrag<<<48, 256>>>(dirs);
    k_gemm<<<NB / 256, 256, SMTOT>>>(z);
    k_ecf<<<dim3(16, NS), 256>>>();
    k_final<<<1, 256>>>(out);
}

// round 16
// speedup vs baseline: 1.2530x; 1.0181x over previous
#include <cuda_runtime.h>
#include <math.h>
#include <stdint.h>

#define NB 65536
#define ND 768
#define NS 64
#define NT 17
#define T_MAX 2.0f
#define DT (T_MAX / (float)NT)
#define EPSV 1e-8f
#define NCH 24                 // k chunks of 32
#define NKK (ND / 8)           // 96

typedef unsigned long long ull;

// ---------------- device scratch ----------------
__device__ float  g_projT[NS * NB];
__device__ float4 g_dirsFrag[NKK * 4 * 32];
__device__ float  g_norm2[NS];
__device__ float  g_colsum[ND];
__device__ float  g_colsq[ND];
__device__ float  g_psum[NS];
__device__ float  g_psq[NS];
__device__ float  g_ecfr[NT * NS];
__device__ float  g_ecfi[NT * NS];

// ---------------- ptx helpers ----------------
__device__ __forceinline__ uint32_t f2tf(float f) {
    uint32_t r; asm("cvt.rna.tf32.f32 %0, %1;" : "=r"(r) : "f"(f)); return r;
}
__device__ __forceinline__ void mma8(float* c, const uint32_t* a,
                                     uint32_t b0, uint32_t b1) {
    asm volatile(
        "mma.sync.aligned.m16n8k8.row.col.f32.tf32.tf32.f32 "
        "{%0,%1,%2,%3},{%4,%5,%6,%7},{%8,%9},{%0,%1,%2,%3};"
        : "+f"(c[0]), "+f"(c[1]), "+f"(c[2]), "+f"(c[3])
        : "r"(a[0]), "r"(a[1]), "r"(a[2]), "r"(a[3]), "r"(b0), "r"(b1));
}
__device__ __forceinline__ uint32_t smem_u32(const void* p) {
    uint32_t a;
    asm("{ .reg .u64 t; cvta.to.shared.u64 t, %1; cvt.u32.u64 %0, t; }" : "=r"(a) : "l"(p));
    return a;
}
__device__ __forceinline__ void cp16(uint32_t s, const void* g) {
    asm volatile("cp.async.cg.shared.global [%0], [%1], 16;" :: "r"(s), "l"(g));
}
#define CP_COMMIT() asm volatile("cp.async.commit_group;" ::: "memory")
#define CP_WAIT2()  asm volatile("cp.async.wait_group 2;" ::: "memory")
#define CP_WAIT0()  asm volatile("cp.async.wait_group 0;" ::: "memory")
__device__ __forceinline__ float lds32(uint32_t a) {
    float v; asm volatile("ld.shared.f32 %0, [%1];" : "=f"(v) : "r"(a)); return v;
}
__device__ __forceinline__ float4 lds128(uint32_t a) {
    float4 v;
    asm volatile("ld.shared.v4.f32 {%0,%1,%2,%3}, [%4];"
                 : "=f"(v.x), "=f"(v.y), "=f"(v.z), "=f"(v.w) : "r"(a));
    return v;
}

// packed f32x2 helpers
__device__ __forceinline__ ull pack2(float lo, float hi) {
    ull r; asm("mov.b64 %0, {%1, %2};" : "=l"(r) : "f"(lo), "f"(hi)); return r;
}
__device__ __forceinline__ void fma2(ull& d, ull a, ull b) {
    asm("fma.rn.f32x2 %0, %1, %2, %0;" : "+l"(d) : "l"(a), "l"(b));
}
__device__ __forceinline__ ull mul2(ull a, ull b) {
    ull r; asm("mul.rn.f32x2 %0, %1, %2;" : "=l"(r) : "l"(a), "l"(b)); return r;
}
__device__ __forceinline__ ull add2(ull a, ull b) {
    ull r; asm("add.rn.f32x2 %0, %1, %2;" : "=l"(r) : "l"(a), "l"(b)); return r;
}
__device__ __forceinline__ ull neg2(ull a) {
    return a ^ 0x8000000080000000ull;
}
__device__ __forceinline__ float2 unpk(ull v) {
    float2 f; asm("mov.b64 {%0, %1}, %2;" : "=f"(f.x), "=f"(f.y) : "l"(v)); return f;
}

// ---------------- kernel 1: dir column norms + accumulator zeroing ---------
__global__ __launch_bounds__(256) void k_dirnorm(const float* __restrict__ dirs) {
    __shared__ float red[4][64];
    const int tid = threadIdx.x;
    const int gidx = blockIdx.x * 256 + tid;

    if (gidx < ND)      { g_colsum[gidx] = 0.f; g_colsq[gidx] = 0.f; }
    if (gidx < NS)      { g_psum[gidx]   = 0.f; g_psq[gidx]   = 0.f; g_norm2[gidx] = 0.f; }
    if (gidx >= 1024 && gidx < 1024 + NT * NS) {
        g_ecfr[gidx - 1024] = 0.f; g_ecfi[gidx - 1024] = 0.f;
    }

    int s = tid & 63, dq = tid >> 6;
    int d0 = blockIdx.x * 12;
    float acc = 0.f;
    #pragma unroll
    for (int j = 0; j < 3; j++) {
        float v = dirs[(size_t)(d0 + j * 4 + dq) * NS + s];
        acc += v * v;
    }
    red[dq][s] = acc;
    __syncthreads();
    if (tid < 64) {
        float v = red[0][s] + red[1][s] + red[2][s] + red[3][s];
        atomicAdd(&g_norm2[s], v);
    }
}

// ---------------- kernel 1b: build tf32 A fragments ------------------------
__global__ void k_prepfrag(const float* __restrict__ dirs) {
    int idx = blockIdx.x * blockDim.x + threadIdx.x;   // 48*256 = 12288
    int kk = idx >> 7, rem = idx & 127;
    int mt = rem >> 5, lane = rem & 31;
    int g = lane >> 2, t = lane & 3;
    int s0 = mt * 16 + g;
    int k0 = kk * 8 + t;
    float i0 = 1.0f / sqrtf(g_norm2[s0]);
    float i1 = 1.0f / sqrtf(g_norm2[s0 + 8]);
    float4 v;
    v.x = __uint_as_float(f2tf(dirs[(size_t)k0 * NS + s0]       * i0));
    v.y = __uint_as_float(f2tf(dirs[(size_t)k0 * NS + s0 + 8]   * i1));
    v.z = __uint_as_float(f2tf(dirs[(size_t)(k0 + 4) * NS + s0]     * i0));
    v.w = __uint_as_float(f2tf(dirs[(size_t)(k0 + 4) * NS + s0 + 8] * i1));
    g_dirsFrag[idx] = v;
}

// ---------------- kernel 2: staged HMMA tf32 GEMM + colstats + psums -------
// (bit-identical to the proven 51.6us version)
#define ZRING (8 * 2 * 4096)          // 64 KB
#define FROFF ZRING
#define SMTOT (ZRING + 3 * 8192)      // 88 KB dynamic

__global__ __launch_bounds__(256, 2) void k_gemm(const float* __restrict__ z) {
    extern __shared__ __align__(128) char smem[];
    __shared__ float scol_s[ND], scol_q[ND];
    __shared__ float ssum[64], ssq[64];

    const uint32_t sb = smem_u32(smem);
    const uint32_t fb = sb + FROFF;
    const int tid = threadIdx.x;
    const int wid = tid >> 5, lane = tid & 31;
    const int g = lane >> 2, t = lane & 3;
    const int nwarp = blockIdx.x * 256 + wid * 32;

    for (int i = tid; i < ND; i += 256) { scol_s[i] = 0.f; scol_q[i] = 0.f; }
    if (tid < 64) { ssum[tid] = 0.f; ssq[tid] = 0.f; }
    __syncthreads();

    const uint32_t wstage = sb + wid * 8192;
    const int fr = lane >> 3, fu = lane & 7;
    const float* zsrc = z + (size_t)nwarp * ND;

    #define FILL_Z(ch) do { \
        uint32_t dst = wstage + ((ch) & 1) * 4096; \
        const float* srcb = zsrc + (ch) * 32; \
        _Pragma("unroll") \
        for (int i = 0; i < 8; i++) { \
            int r = i * 4 + fr; \
            cp16(dst + r * 128 + ((fu ^ (r & 7)) << 4), \
                 srcb + (size_t)r * ND + fu * 4); \
        } \
        CP_COMMIT(); \
    } while (0)

    #define FILL_F(ch) do { \
        uint32_t dst = fb + ((ch) % 3) * 8192 + tid * 32; \
        const float4* srcb = g_dirsFrag + (ch) * 512 + tid * 2; \
        cp16(dst,      srcb); \
        cp16(dst + 16, srcb + 1); \
        CP_COMMIT(); \
    } while (0)

    FILL_F(0); FILL_Z(0); FILL_F(1); FILL_Z(1);

    float c[4][4][4];
    #pragma unroll
    for (int mt = 0; mt < 4; mt++)
        #pragma unroll
        for (int nt = 0; nt < 4; nt++)
            #pragma unroll
            for (int r = 0; r < 4; r++) c[mt][nt][r] = 0.f;

    for (int ch = 0; ch < NCH; ch++) {
        if (ch < NCH - 1) { CP_WAIT2(); } else { CP_WAIT0(); }
        __syncthreads();

        if (ch + 2 < NCH) FILL_F(ch + 2);

        const uint32_t zstage = wstage + (ch & 1) * 4096;
        const uint32_t fstage = fb + (ch % 3) * 8192;

        #pragma unroll
        for (int kk = 0; kk < 4; kk++) {
            uint32_t a[4][4];
            #pragma unroll
            for (int mt = 0; mt < 4; mt++) {
                float4 v = lds128(fstage + ((kk * 128 + mt * 32 + lane) << 4));
                a[mt][0] = __float_as_uint(v.x);
                a[mt][1] = __float_as_uint(v.y);
                a[mt][2] = __float_as_uint(v.z);
                a[mt][3] = __float_as_uint(v.w);
            }
            uint32_t b0[4], b1[4];
            #pragma unroll
            for (int nt = 0; nt < 4; nt++) {
                int row = nt * 8 + g;
                uint32_t base = zstage + row * 128 + t * 4;
                b0[nt] = __float_as_uint(lds32(base + (((2 * kk)     ^ g) << 4)));
                b1[nt] = __float_as_uint(lds32(base + (((2 * kk + 1) ^ g) << 4)));
            }
            #pragma unroll
            for (int mt = 0; mt < 4; mt++)
                #pragma unroll
                for (int nt = 0; nt < 4; nt++)
                    mma8(c[mt][nt], a[mt], b0[nt], b1[nt]);
        }

        {
            const int cu = lane >> 2, co = (lane & 3) * 4;
            float cs = 0.f, cq = 0.f;
            #pragma unroll
            for (int r = 0; r < 32; r++) {
                float v = lds32(zstage + r * 128 + ((cu ^ (r & 7)) << 4) + co);
                cs += v; cq += v * v;
            }
            atomicAdd(&scol_s[ch * 32 + lane], cs);
            atomicAdd(&scol_q[ch * 32 + lane], cq);
        }

        if (ch + 2 < NCH) FILL_Z(ch + 2);
    }

    #pragma unroll
    for (int mt = 0; mt < 4; mt++) {
        float su0 = 0.f, su1 = 0.f, sq0 = 0.f, sq1 = 0.f;
        int s0 = mt * 16 + g;
        #pragma unroll
        for (int nt = 0; nt < 4; nt++) {
            float d0 = c[mt][nt][0], d1 = c[mt][nt][1];
            float d2 = c[mt][nt][2], d3 = c[mt][nt][3];
            int n = nwarp + nt * 8 + t * 2;
            *(float2*)(g_projT + (size_t)s0 * NB + n)       = make_float2(d0, d1);
            *(float2*)(g_projT + (size_t)(s0 + 8) * NB + n) = make_float2(d2, d3);
            su0 += d0 + d1; sq0 += d0 * d0 + d1 * d1;
            su1 += d2 + d3; sq1 += d2 * d2 + d3 * d3;
        }
        #pragma unroll
        for (int off = 1; off < 4; off <<= 1) {
            su0 += __shfl_xor_sync(0xffffffffu, su0, off);
            sq0 += __shfl_xor_sync(0xffffffffu, sq0, off);
            su1 += __shfl_xor_sync(0xffffffffu, su1, off);
            sq1 += __shfl_xor_sync(0xffffffffu, sq1, off);
        }
        if (t == 0) {
            atomicAdd(&ssum[s0], su0);     atomicAdd(&ssq[s0], sq0);
            atomicAdd(&ssum[s0 + 8], su1); atomicAdd(&ssq[s0 + 8], sq1);
        }
    }
    __syncthreads();
    if (tid < 64) {
        atomicAdd(&g_psum[tid], ssum[tid]);
        atomicAdd(&g_psq[tid],  ssq[tid]);
    }
    #pragma unroll
    for (int rep = 0; rep < 3; rep++) {
        int col = rep * 256 + tid;
        atomicAdd(&g_colsum[col], scol_s[col]);
        atomicAdd(&g_colsq[col],  scol_q[col]);
    }
}

// ---------------- kernel 6: ECF, even/odd split Chebyshev chains -----------
// Two independent step-2th chains (odd multiples 1..17, even 2..16):
// halves the serial dependency chain and doubles ILP, same op count.
__global__ __launch_bounds__(256) void k_ecf() {
    int s = blockIdx.y;
    float pmean = g_psum[s] / (float)NB;
    float pvar = (g_psq[s] - (float)NB * pmean * pmean) / (float)(NB - 1);
    float invstd = 1.0f / (sqrtf(fmaxf(pvar, 0.f)) + EPSV);

    size_t basep = (size_t)s * NB + blockIdx.x * 4096;
    const float2* src = (const float2*)(g_projT + basep);

    float2 pv[8];
    #pragma unroll
    for (int i = 0; i < 8; i++) pv[i] = src[threadIdx.x + i * 256];

    ull CR[NT], CI[NT];   // index m-1 for multiple m
    #pragma unroll
    for (int j = 0; j < NT; j++) { CR[j] = 0ull; CI[j] = 0ull; }

    #pragma unroll 2
    for (int i = 0; i < 8; i++) {
        float p0 = (pv[i].x - pmean) * invstd;
        float p1 = (pv[i].y - pmean) * invstd;
        float c0, s0, c1v, s1v;
        __sincosf(DT * p0, &s0, &c0);
        __sincosf(DT * p1, &s1v, &c1v);
        ull c1 = pack2(c0, c1v);
        ull s1 = pack2(s0, s1v);
        // double angle: c2 = 2c1^2 - 1, s2 = 2 c1 s1
        ull twoc1 = add2(c1, c1);
        ull c2 = pack2(-1.f, -1.f); fma2(c2, twoc1, c1);
        ull s2 = mul2(twoc1, s1);
        ull twoc2 = add2(c2, c2);

        // odd chain: cur = (c1,s1), prev = (cos(-th)=c1, sin(-th)=-s1)
        ull ccA = c1, ssA = s1;
        ull ncpA = neg2(c1), nspA = s1;
        // even chain: cur = (c2,s2), prev = (cos0=1, sin0=0)
        ull ccB = c2, ssB = s2;
        ull ncpB = pack2(-1.f, -1.f), nspB = 0ull;

        #pragma unroll
        for (int j = 0; j < 8; j++) {       // multiples 2j+1 and 2j+2
            CR[2 * j]     = add2(CR[2 * j],     ccA);
            CI[2 * j]     = add2(CI[2 * j],     ssA);
            CR[2 * j + 1] = add2(CR[2 * j + 1], ccB);
            CI[2 * j + 1] = add2(CI[2 * j + 1], ssB);
            ull cnA = ncpA; fma2(cnA, twoc2, ccA);
            ull snA = nspA; fma2(snA, twoc2, ssA);
            ull cnB = ncpB; fma2(cnB, twoc2, ccB);
            ull snB = nspB; fma2(snB, twoc2, ssB);
            ncpA = neg2(ccA); nspA = neg2(ssA); ccA = cnA; ssA = snA;
            ncpB = neg2(ccB); nspB = neg2(ssB); ccB = cnB; ssB = snB;
        }
        // multiple 17 (odd chain's 9th element)
        CR[16] = add2(CR[16], ccA);
        CI[16] = add2(CI[16], ssA);
    }

    unsigned msk = 0xffffffffu;
    #pragma unroll
    for (int j = 0; j < NT; j++) {
        float2 r2 = unpk(CR[j]);
        float2 i2 = unpk(CI[j]);
        float r = r2.x + r2.y, im = i2.x + i2.y;
        #pragma unroll
        for (int off = 16; off; off >>= 1) {
            r  += __shfl_down_sync(msk, r,  off);
            im += __shfl_down_sync(msk, im, off);
        }
        if ((threadIdx.x & 31) == 0) {
            atomicAdd(&g_ecfr[j * NS + s], r);
            atomicAdd(&g_ecfi[j * NS + s], im);
        }
    }
}

// ---------------- kernel 7: final scalar loss -------------------------------
__global__ __launch_bounds__(256) void k_final(float* __restrict__ out) {
    __shared__ float red[256];
    int t = threadIdx.x;
    float acc = 0.f;

    for (int d = t; d < ND; d += 256) {
        float mean = g_colsum[d] / (float)NB;
        float var = (g_colsq[d] - (float)NB * mean * mean) / (float)(NB - 1);
        float stdv = sqrtf(fmaxf(var, 0.f));
        acc += fmaxf(1.0f - stdv, 0.f) * (1.0f / (float)ND);
    }

    for (int idx = t; idx < NT * NS; idx += 256) {
        int j = idx / NS;
        float tj = DT * (float)(j + 1);
        float er = g_ecfr[idx] / (float)NB;
        float ei = g_ecfi[idx] / (float)NB;
        float tcf = expf(-0.5f * tj * tj);
        float term = er * er + ei * ei - 2.0f * er * tcf + tcf * tcf;
        float w = DT * ((j == 0 || j == NT - 1) ? 0.5f : 1.0f);
        acc += w * term * (1.0f / (float)NS);
    }

    red[t] = acc;
    __syncthreads();
    for (int off = 128; off; off >>= 1) {
        if (t < off) red[t] += red[t + off];
        __syncthreads();
    }
    if (t == 0) out[0] = red[0];
}

// ---------------- launch -----------------------------------------------------
extern "C" void kernel_launch(void* const* d_in, const int* in_sizes, int n_in,
                              void* d_out, int out_size) {
    const float* z    = (const float*)d_in[0];   // [65536, 768]
    const float* dirs = (const float*)d_in[1];   // [768, 64]
    float* out = (float*)d_out;

    cudaFuncSetAttribute(k_gemm, cudaFuncAttributeMaxDynamicSharedMemorySize, SMTOT);

    k_dirnorm<<<64, 256>>>(dirs);
    k_prepfrag<<<48, 256>>>(dirs);
    k_gemm<<<NB / 256, 256, SMTOT>>>(z);
    k_ecf<<<dim3(16, NS), 256>>>();
    k_final<<<1, 256>>>(out);
}

// round 17
// speedup vs baseline: 1.3143x; 1.0489x over previous
#include <cuda_runtime.h>
#include <math.h>
#include <stdint.h>

#define NB 65536
#define ND 768
#define NS 64
#define NT 17
#define T_MAX 2.0f
#define DT (T_MAX / (float)NT)
#define EPSV 1e-8f
#define NCH 24                 // k chunks of 32
#define NKK (ND / 8)           // 96

typedef unsigned long long ull;

// ---------------- device scratch ----------------
__device__ float  g_projT[NS * NB];
__device__ float4 g_dirsFrag[NKK * 4 * 32];
__device__ float  g_norm2[NS];
__device__ float  g_colsum[ND];
__device__ float  g_colsq[ND];
__device__ float  g_psum[NS];
__device__ float  g_psq[NS];
__device__ float  g_ecfr[NT * NS];
__device__ float  g_ecfi[NT * NS];

// ---------------- ptx helpers ----------------
__device__ __forceinline__ uint32_t f2tf(float f) {
    uint32_t r; asm("cvt.rna.tf32.f32 %0, %1;" : "=r"(r) : "f"(f)); return r;
}
__device__ __forceinline__ void mma8(float* c, const uint32_t* a,
                                     uint32_t b0, uint32_t b1) {
    asm volatile(
        "mma.sync.aligned.m16n8k8.row.col.f32.tf32.tf32.f32 "
        "{%0,%1,%2,%3},{%4,%5,%6,%7},{%8,%9},{%0,%1,%2,%3};"
        : "+f"(c[0]), "+f"(c[1]), "+f"(c[2]), "+f"(c[3])
        : "r"(a[0]), "r"(a[1]), "r"(a[2]), "r"(a[3]), "r"(b0), "r"(b1));
}
__device__ __forceinline__ uint32_t smem_u32(const void* p) {
    uint32_t a;
    asm("{ .reg .u64 t; cvta.to.shared.u64 t, %1; cvt.u32.u64 %0, t; }" : "=r"(a) : "l"(p));
    return a;
}
__device__ __forceinline__ void cp16(uint32_t s, const void* g) {
    asm volatile("cp.async.cg.shared.global [%0], [%1], 16;" :: "r"(s), "l"(g));
}
#define CP_COMMIT() asm volatile("cp.async.commit_group;" ::: "memory")
#define CP_WAIT2()  asm volatile("cp.async.wait_group 2;" ::: "memory")
#define CP_WAIT0()  asm volatile("cp.async.wait_group 0;" ::: "memory")
__device__ __forceinline__ float lds32(uint32_t a) {
    float v; asm volatile("ld.shared.f32 %0, [%1];" : "=f"(v) : "r"(a)); return v;
}
__device__ __forceinline__ float4 lds128(uint32_t a) {
    float4 v;
    asm volatile("ld.shared.v4.f32 {%0,%1,%2,%3}, [%4];"
                 : "=f"(v.x), "=f"(v.y), "=f"(v.z), "=f"(v.w) : "r"(a));
    return v;
}

// packed f32x2 helpers
__device__ __forceinline__ ull pack2(float lo, float hi) {
    ull r; asm("mov.b64 %0, {%1, %2};" : "=l"(r) : "f"(lo), "f"(hi)); return r;
}
__device__ __forceinline__ void fma2(ull& d, ull a, ull b) {
    asm("fma.rn.f32x2 %0, %1, %2, %0;" : "+l"(d) : "l"(a), "l"(b));
}
__device__ __forceinline__ ull mul2(ull a, ull b) {
    ull r; asm("mul.rn.f32x2 %0, %1, %2;" : "=l"(r) : "l"(a), "l"(b)); return r;
}
__device__ __forceinline__ ull add2(ull a, ull b) {
    ull r; asm("add.rn.f32x2 %0, %1, %2;" : "=l"(r) : "l"(a), "l"(b)); return r;
}
__device__ __forceinline__ ull neg2(ull a) {
    return a ^ 0x8000000080000000ull;
}
__device__ __forceinline__ float2 unpk(ull v) {
    float2 f; asm("mov.b64 {%0, %1}, %2;" : "=f"(f.x), "=f"(f.y) : "l"(v)); return f;
}

// ---------------- kernel 1: dir column norms + accumulator zeroing ---------
__global__ __launch_bounds__(256) void k_dirnorm(const float* __restrict__ dirs) {
    __shared__ float red[4][64];
    const int tid = threadIdx.x;
    const int gidx = blockIdx.x * 256 + tid;

    if (gidx < ND)      { g_colsum[gidx] = 0.f; g_colsq[gidx] = 0.f; }
    if (gidx < NS)      { g_psum[gidx]   = 0.f; g_psq[gidx]   = 0.f; g_norm2[gidx] = 0.f; }
    if (gidx >= 1024 && gidx < 1024 + NT * NS) {
        g_ecfr[gidx - 1024] = 0.f; g_ecfi[gidx - 1024] = 0.f;
    }

    int s = tid & 63, dq = tid >> 6;
    int d0 = blockIdx.x * 12;
    float acc = 0.f;
    #pragma unroll
    for (int j = 0; j < 3; j++) {
        float v = dirs[(size_t)(d0 + j * 4 + dq) * NS + s];
        acc += v * v;
    }
    red[dq][s] = acc;
    __syncthreads();
    if (tid < 64) {
        float v = red[0][s] + red[1][s] + red[2][s] + red[3][s];
        atomicAdd(&g_norm2[s], v);
    }
}

// ---------------- kernel 1b: build tf32 A fragments ------------------------
__global__ void k_prepfrag(const float* __restrict__ dirs) {
    int idx = blockIdx.x * blockDim.x + threadIdx.x;   // 48*256 = 12288
    int kk = idx >> 7, rem = idx & 127;
    int mt = rem >> 5, lane = rem & 31;
    int g = lane >> 2, t = lane & 3;
    int s0 = mt * 16 + g;
    int k0 = kk * 8 + t;
    float i0 = 1.0f / sqrtf(g_norm2[s0]);
    float i1 = 1.0f / sqrtf(g_norm2[s0 + 8]);
    float4 v;
    v.x = __uint_as_float(f2tf(dirs[(size_t)k0 * NS + s0]       * i0));
    v.y = __uint_as_float(f2tf(dirs[(size_t)k0 * NS + s0 + 8]   * i1));
    v.z = __uint_as_float(f2tf(dirs[(size_t)(k0 + 4) * NS + s0]     * i0));
    v.w = __uint_as_float(f2tf(dirs[(size_t)(k0 + 4) * NS + s0 + 8] * i1));
    g_dirsFrag[idx] = v;
}

// ---------------- kernel 2: staged HMMA tf32 GEMM + colstats + psums -------
// (bit-identical to the proven 51.6us version)
#define ZRING (8 * 2 * 4096)          // 64 KB
#define FROFF ZRING
#define SMTOT (ZRING + 3 * 8192)      // 88 KB dynamic

__global__ __launch_bounds__(256, 2) void k_gemm(const float* __restrict__ z) {
    extern __shared__ __align__(128) char smem[];
    __shared__ float scol_s[ND], scol_q[ND];
    __shared__ float ssum[64], ssq[64];

    const uint32_t sb = smem_u32(smem);
    const uint32_t fb = sb + FROFF;
    const int tid = threadIdx.x;
    const int wid = tid >> 5, lane = tid & 31;
    const int g = lane >> 2, t = lane & 3;
    const int nwarp = blockIdx.x * 256 + wid * 32;

    for (int i = tid; i < ND; i += 256) { scol_s[i] = 0.f; scol_q[i] = 0.f; }
    if (tid < 64) { ssum[tid] = 0.f; ssq[tid] = 0.f; }
    __syncthreads();

    const uint32_t wstage = sb + wid * 8192;
    const int fr = lane >> 3, fu = lane & 7;
    const float* zsrc = z + (size_t)nwarp * ND;

    #define FILL_Z(ch) do { \
        uint32_t dst = wstage + ((ch) & 1) * 4096; \
        const float* srcb = zsrc + (ch) * 32; \
        _Pragma("unroll") \
        for (int i = 0; i < 8; i++) { \
            int r = i * 4 + fr; \
            cp16(dst + r * 128 + ((fu ^ (r & 7)) << 4), \
                 srcb + (size_t)r * ND + fu * 4); \
        } \
        CP_COMMIT(); \
    } while (0)

    #define FILL_F(ch) do { \
        uint32_t dst = fb + ((ch) % 3) * 8192 + tid * 32; \
        const float4* srcb = g_dirsFrag + (ch) * 512 + tid * 2; \
        cp16(dst,      srcb); \
        cp16(dst + 16, srcb + 1); \
        CP_COMMIT(); \
    } while (0)

    FILL_F(0); FILL_Z(0); FILL_F(1); FILL_Z(1);

    float c[4][4][4];
    #pragma unroll
    for (int mt = 0; mt < 4; mt++)
        #pragma unroll
        for (int nt = 0; nt < 4; nt++)
            #pragma unroll
            for (int r = 0; r < 4; r++) c[mt][nt][r] = 0.f;

    for (int ch = 0; ch < NCH; ch++) {
        if (ch < NCH - 1) { CP_WAIT2(); } else { CP_WAIT0(); }
        __syncthreads();

        if (ch + 2 < NCH) FILL_F(ch + 2);

        const uint32_t zstage = wstage + (ch & 1) * 4096;
        const uint32_t fstage = fb + (ch % 3) * 8192;

        #pragma unroll
        for (int kk = 0; kk < 4; kk++) {
            uint32_t a[4][4];
            #pragma unroll
            for (int mt = 0; mt < 4; mt++) {
                float4 v = lds128(fstage + ((kk * 128 + mt * 32 + lane) << 4));
                a[mt][0] = __float_as_uint(v.x);
                a[mt][1] = __float_as_uint(v.y);
                a[mt][2] = __float_as_uint(v.z);
                a[mt][3] = __float_as_uint(v.w);
            }
            uint32_t b0[4], b1[4];
            #pragma unroll
            for (int nt = 0; nt < 4; nt++) {
                int row = nt * 8 + g;
                uint32_t base = zstage + row * 128 + t * 4;
                b0[nt] = __float_as_uint(lds32(base + (((2 * kk)     ^ g) << 4)));
                b1[nt] = __float_as_uint(lds32(base + (((2 * kk + 1) ^ g) << 4)));
            }
            #pragma unroll
            for (int mt = 0; mt < 4; mt++)
                #pragma unroll
                for (int nt = 0; nt < 4; nt++)
                    mma8(c[mt][nt], a[mt], b0[nt], b1[nt]);
        }

        {
            const int cu = lane >> 2, co = (lane & 3) * 4;
            float cs = 0.f, cq = 0.f;
            #pragma unroll
            for (int r = 0; r < 32; r++) {
                float v = lds32(zstage + r * 128 + ((cu ^ (r & 7)) << 4) + co);
                cs += v; cq += v * v;
            }
            atomicAdd(&scol_s[ch * 32 + lane], cs);
            atomicAdd(&scol_q[ch * 32 + lane], cq);
        }

        if (ch + 2 < NCH) FILL_Z(ch + 2);
    }

    #pragma unroll
    for (int mt = 0; mt < 4; mt++) {
        float su0 = 0.f, su1 = 0.f, sq0 = 0.f, sq1 = 0.f;
        int s0 = mt * 16 + g;
        #pragma unroll
        for (int nt = 0; nt < 4; nt++) {
            float d0 = c[mt][nt][0], d1 = c[mt][nt][1];
            float d2 = c[mt][nt][2], d3 = c[mt][nt][3];
            int n = nwarp + nt * 8 + t * 2;
            *(float2*)(g_projT + (size_t)s0 * NB + n)       = make_float2(d0, d1);
            *(float2*)(g_projT + (size_t)(s0 + 8) * NB + n) = make_float2(d2, d3);
            su0 += d0 + d1; sq0 += d0 * d0 + d1 * d1;
            su1 += d2 + d3; sq1 += d2 * d2 + d3 * d3;
        }
        #pragma unroll
        for (int off = 1; off < 4; off <<= 1) {
            su0 += __shfl_xor_sync(0xffffffffu, su0, off);
            sq0 += __shfl_xor_sync(0xffffffffu, sq0, off);
            su1 += __shfl_xor_sync(0xffffffffu, su1, off);
            sq1 += __shfl_xor_sync(0xffffffffu, sq1, off);
        }
        if (t == 0) {
            atomicAdd(&ssum[s0], su0);     atomicAdd(&ssq[s0], sq0);
            atomicAdd(&ssum[s0 + 8], su1); atomicAdd(&ssq[s0 + 8], sq1);
        }
    }
    __syncthreads();
    if (tid < 64) {
        atomicAdd(&g_psum[tid], ssum[tid]);
        atomicAdd(&g_psq[tid],  ssq[tid]);
    }
    #pragma unroll
    for (int rep = 0; rep < 3; rep++) {
        int col = rep * 256 + tid;
        atomicAdd(&g_colsum[col], scol_s[col]);
        atomicAdd(&g_colsq[col],  scol_q[col]);
    }
}

// ---------------- kernel 6: ECF, warp-specialized odd/even harmonics -------
// Block covers 2048 elements of one s. Warps 0-3: odd multiples 1..17
// (9 accumulators); warps 4-7: even multiples 2..16 (8 accumulators).
// Both run step-2theta Chebyshev; accumulator state halves -> higher occ.
__global__ __launch_bounds__(256) void k_ecf() {
    int s = blockIdx.y;
    float pmean = g_psum[s] / (float)NB;
    float pvar = (g_psq[s] - (float)NB * pmean * pmean) / (float)(NB - 1);
    float invstd = 1.0f / (sqrtf(fmaxf(pvar, 0.f)) + EPSV);

    const int wid = threadIdx.x >> 5;
    const int half = wid >> 2;            // 0: odd, 1: even
    const int wtid = threadIdx.x & 127;   // thread within half-group

    size_t basep = (size_t)s * NB + blockIdx.x * 2048;
    const float2* src = (const float2*)(g_projT + basep);
    unsigned msk = 0xffffffffu;

    if (half == 0) {
        ull CR[9], CI[9];
        #pragma unroll
        for (int j = 0; j < 9; j++) { CR[j] = 0ull; CI[j] = 0ull; }

        #pragma unroll 2
        for (int i = 0; i < 8; i++) {
            float2 pv = src[wtid + i * 128];
            float p0 = (pv.x - pmean) * invstd;
            float p1 = (pv.y - pmean) * invstd;
            float c0, s0, c1v, s1v;
            __sincosf(DT * p0, &s0, &c0);
            __sincosf(DT * p1, &s1v, &c1v);
            ull c1 = pack2(c0, c1v);
            ull s1 = pack2(s0, s1v);
            ull twoc1 = add2(c1, c1);
            ull c2 = pack2(-1.f, -1.f); fma2(c2, twoc1, c1);
            ull twoc2 = add2(c2, c2);
            // odd chain: cur=(c1,s1) [m=1], prev=(c1,-s1) [m=-1]
            ull cc = c1, ss = s1;
            ull ncp = neg2(c1), nsp = s1;
            #pragma unroll
            for (int j = 0; j < 9; j++) {      // multiples 1,3,...,17
                CR[j] = add2(CR[j], cc);
                CI[j] = add2(CI[j], ss);
                ull cn = ncp; fma2(cn, twoc2, cc);
                ull sn = nsp; fma2(sn, twoc2, ss);
                ncp = neg2(cc); nsp = neg2(ss);
                cc = cn; ss = sn;
            }
        }
        #pragma unroll
        for (int j = 0; j < 9; j++) {
            float2 r2 = unpk(CR[j]);
            float2 i2 = unpk(CI[j]);
            float r = r2.x + r2.y, im = i2.x + i2.y;
            #pragma unroll
            for (int off = 16; off; off >>= 1) {
                r  += __shfl_down_sync(msk, r,  off);
                im += __shfl_down_sync(msk, im, off);
            }
            if ((threadIdx.x & 31) == 0) {
                atomicAdd(&g_ecfr[(2 * j) * NS + s], r);   // multiple 2j+1 -> idx 2j
                atomicAdd(&g_ecfi[(2 * j) * NS + s], im);
            }
        }
    } else {
        ull CR[8], CI[8];
        #pragma unroll
        for (int j = 0; j < 8; j++) { CR[j] = 0ull; CI[j] = 0ull; }

        #pragma unroll 2
        for (int i = 0; i < 8; i++) {
            float2 pv = src[wtid + i * 128];
            float p0 = (pv.x - pmean) * invstd;
            float p1 = (pv.y - pmean) * invstd;
            float c0, s0, c1v, s1v;
            __sincosf(DT * p0, &s0, &c0);
            __sincosf(DT * p1, &s1v, &c1v);
            ull c1 = pack2(c0, c1v);
            ull s1 = pack2(s0, s1v);
            ull twoc1 = add2(c1, c1);
            ull c2 = pack2(-1.f, -1.f); fma2(c2, twoc1, c1);
            ull s2 = mul2(twoc1, s1);
            ull twoc2 = add2(c2, c2);
            // even chain: cur=(c2,s2) [m=2], prev=(1,0) [m=0]
            ull cc = c2, ss = s2;
            ull ncp = pack2(-1.f, -1.f), nsp = 0ull;
            #pragma unroll
            for (int j = 0; j < 8; j++) {      // multiples 2,4,...,16
                CR[j] = add2(CR[j], cc);
                CI[j] = add2(CI[j], ss);
                ull cn = ncp; fma2(cn, twoc2, cc);
                ull sn = nsp; fma2(sn, twoc2, ss);
                ncp = neg2(cc); nsp = neg2(ss);
                cc = cn; ss = sn;
            }
        }
        #pragma unroll
        for (int j = 0; j < 8; j++) {
            float2 r2 = unpk(CR[j]);
            float2 i2 = unpk(CI[j]);
            float r = r2.x + r2.y, im = i2.x + i2.y;
            #pragma unroll
            for (int off = 16; off; off >>= 1) {
                r  += __shfl_down_sync(msk, r,  off);
                im += __shfl_down_sync(msk, im, off);
            }
            if ((threadIdx.x & 31) == 0) {
                atomicAdd(&g_ecfr[(2 * j + 1) * NS + s], r);  // multiple 2j+2 -> idx 2j+1
                atomicAdd(&g_ecfi[(2 * j + 1) * NS + s], im);
            }
        }
    }
}

// ---------------- kernel 7: final scalar loss -------------------------------
__global__ __launch_bounds__(256) void k_final(float* __restrict__ out) {
    __shared__ float red[256];
    int t = threadIdx.x;
    float acc = 0.f;

    for (int d = t; d < ND; d += 256) {
        float mean = g_colsum[d] / (float)NB;
        float var = (g_colsq[d] - (float)NB * mean * mean) / (float)(NB - 1);
        float stdv = sqrtf(fmaxf(var, 0.f));
        acc += fmaxf(1.0f - stdv, 0.f) * (1.0f / (float)ND);
    }

    for (int idx = t; idx < NT * NS; idx += 256) {
        int j = idx / NS;
        float tj = DT * (float)(j + 1);
        float er = g_ecfr[idx] / (float)NB;
        float ei = g_ecfi[idx] / (float)NB;
        float tcf = expf(-0.5f * tj * tj);
        float term = er * er + ei * ei - 2.0f * er * tcf + tcf * tcf;
        float w = DT * ((j == 0 || j == NT - 1) ? 0.5f : 1.0f);
        acc += w * term * (1.0f / (float)NS);
    }

    red[t] = acc;
    __syncthreads();
    for (int off = 128; off; off >>= 1) {
        if (t < off) red[t] += red[t + off];
        __syncthreads();
    }
    if (t == 0) out[0] = red[0];
}

// ---------------- launch -----------------------------------------------------
extern "C" void kernel_launch(void* const* d_in, const int* in_sizes, int n_in,
                              void* d_out, int out_size) {
    const float* z    = (const float*)d_in[0];   // [65536, 768]
    const float* dirs = (const float*)d_in[1];   // [768, 64]
    float* out = (float*)d_out;

    cudaFuncSetAttribute(k_gemm, cudaFuncAttributeMaxDynamicSharedMemorySize, SMTOT);

    k_dirnorm<<<64, 256>>>(dirs);
    k_prepfrag<<<48, 256>>>(dirs);
    k_gemm<<<NB / 256, 256, SMTOT>>>(z);
    k_ecf<<<dim3(32, NS), 256>>>();
    k_final<<<1, 256>>>(out);
}